// round 3
// baseline (speedup 1.0000x reference)
#include <cuda_runtime.h>
#include <mma.h>
#include <math.h>

using namespace nvcuda;

#define NBAG 512
#define MS 8
#define TT 64
#define BDIM 4096          // NBAG*MS
#define INDIM 360
#define HH 230
#define H2 460
#define G3 690
#define NOUT 53
#define NDOCS 32
#define NENT 8
#define HP 232             // padded H (mult of 8)
#define M_TOT (BDIM * TT)  // 262144

// ------------------- scratch (device globals; zero-initialized at module load) -------------------
__device__ float g_xg[2ull * M_TOT * G3];                 // [dir][m=b*T+t][690]
// slab-indexed hidden states. fwd: h_t lives at slab t+1 (slab 0 = zeros, never written).
// rev: h_t lives at slab t (slab TT = zeros, never written). pad cols 230,231 never written.
__device__ float g_hf[(size_t)(TT + 1) * BDIM * HP];
__device__ float g_hr[(size_t)(TT + 1) * BDIM * HP];
__device__ float g_scores[(size_t)BDIM * TT];             // [b][t]
__device__ float g_wordvec[(size_t)BDIM * H2];            // [b][460]

// =================== 1. input GEMM (tf32 wmma): xg = bag @ W_ih^T + b_ih ===================
// M=262144, N=690 (pad 704), K=360.  BM=128, BN=64, BK=16, 8 warps (4m x 2n), warp 32x32.
__global__ __launch_bounds__(256) void input_gemm_wmma(
    const float* __restrict__ A,
    const float* __restrict__ Wf, const float* __restrict__ bf_,
    const float* __restrict__ Wr, const float* __restrict__ br_)
{
    __shared__ float sA[128 * 20];   // [m][k], ld 20
    __shared__ float sB[16 * 68];    // [k][n], ld 68
    __shared__ float sC[128 * 64];   // epilogue staging

    const int dir = blockIdx.z;
    const float* W    = dir ? Wr : Wf;
    const float* bias = dir ? br_ : bf_;
    float* C = g_xg + (size_t)dir * M_TOT * G3;

    const int n0 = blockIdx.x * 64;
    const int m0 = blockIdx.y * 128;
    const int tid = threadIdx.x;
    const int warp = tid >> 5;
    const int wm = warp >> 1, wn = warp & 1;

    wmma::fragment<wmma::accumulator, 16, 16, 8, float> acc[2][2];
    #pragma unroll
    for (int i = 0; i < 2; i++)
        #pragma unroll
        for (int j = 0; j < 2; j++) wmma::fill_fragment(acc[i][j], 0.f);

    for (int k0 = 0; k0 < INDIM; k0 += 16) {
        __syncthreads();
        {   // stage A 128x16: thread -> row m, 8 k's
            int m = tid >> 1, koff = (tid & 1) * 8;
            const float* ap = A + (size_t)(m0 + m) * INDIM;
            #pragma unroll
            for (int q = 0; q < 8; q++) {
                int k = k0 + koff + q;
                sA[m * 20 + koff + q] = (k < INDIM) ? ap[k] : 0.f;
            }
        }
        {   // stage B 16x64: thread -> k, 4 n's (coalesced along k)
            int k = tid & 15, ng = tid >> 4;
            int kk = k0 + k;
            #pragma unroll
            for (int q = 0; q < 4; q++) {
                int n = ng * 4 + q;
                int nn = n0 + n;
                sB[k * 68 + n] = (nn < G3 && kk < INDIM) ? W[(size_t)nn * INDIM + kk] : 0.f;
            }
        }
        __syncthreads();
        #pragma unroll
        for (int kk = 0; kk < 16; kk += 8) {
            wmma::fragment<wmma::matrix_b, 16, 16, 8, wmma::precision::tf32, wmma::row_major> bfr[2];
            #pragma unroll
            for (int ni = 0; ni < 2; ni++) {
                wmma::load_matrix_sync(bfr[ni], &sB[kk * 68 + wn * 32 + ni * 16], 68);
                #pragma unroll
                for (int e = 0; e < bfr[ni].num_elements; e++)
                    bfr[ni].x[e] = wmma::__float_to_tf32(bfr[ni].x[e]);
            }
            #pragma unroll
            for (int mi = 0; mi < 2; mi++) {
                wmma::fragment<wmma::matrix_a, 16, 16, 8, wmma::precision::tf32, wmma::row_major> af;
                wmma::load_matrix_sync(af, &sA[(wm * 32 + mi * 16) * 20 + kk], 20);
                #pragma unroll
                for (int e = 0; e < af.num_elements; e++)
                    af.x[e] = wmma::__float_to_tf32(af.x[e]);
                #pragma unroll
                for (int ni = 0; ni < 2; ni++)
                    wmma::mma_sync(acc[mi][ni], af, bfr[ni], acc[mi][ni]);
            }
        }
    }
    __syncthreads();
    #pragma unroll
    for (int mi = 0; mi < 2; mi++)
        #pragma unroll
        for (int ni = 0; ni < 2; ni++)
            wmma::store_matrix_sync(&sC[(wm * 32 + mi * 16) * 64 + wn * 32 + ni * 16],
                                    acc[mi][ni], 64, wmma::mem_row_major);
    __syncthreads();
    {   // write out: warp lanes cover consecutive cols -> coalesced
        int col = tid & 63;
        int r0 = tid >> 6;
        #pragma unroll 8
        for (int i = 0; i < 32; i++) {
            int m = r0 * 32 + i;
            int n = n0 + col;
            if (n < G3)
                C[(size_t)(m0 + m) * G3 + n] = sC[m * 64 + col] + bias[n];
        }
    }
}

// =================== 2. GRU step (tf32 wmma, 3 gates fused) ===================
// per block: 64 batch rows x 64 j's, all 3 gate GEMMs. K = 232 (padded, zeros beyond 229).
__global__ __launch_bounds__(256) void gru_step_wmma(
    const float* __restrict__ Whhf, const float* __restrict__ bhhf,
    const float* __restrict__ Whhr, const float* __restrict__ bhhr,
    int s)
{
    __shared__ float sH[64 * 20];        // [m][k], ld 20
    __shared__ float sB[3 * 16 * 68];    // [g][k][j], ld 68
    __shared__ float sC[8 * 3 * 256];    // per-warp, per-gate 16x16

    const int dir = blockIdx.z;
    const int t = dir ? (TT - 1 - s) : s;
    const float* W   = dir ? Whhr : Whhf;
    const float* bhh = dir ? bhhr : bhhf;
    const float* xg = g_xg + (size_t)dir * M_TOT * G3;
    float* hbase = dir ? g_hr : g_hf;
    const int slab_prev = dir ? (t + 1) : t;       // fwd step s: prev at slab s (== t)
    const int slab_out  = dir ? t : (t + 1);
    const float* hprev = hbase + (size_t)slab_prev * BDIM * HP;
    float* hout = hbase + (size_t)slab_out * BDIM * HP;

    const int j0 = blockIdx.x * 64;
    const int b0 = blockIdx.y * 64;
    const int tid = threadIdx.x;
    const int warp = tid >> 5, lane = tid & 31;
    const int wm = warp >> 1, wn = warp & 1;

    wmma::fragment<wmma::accumulator, 16, 16, 8, float> acc[3][2];
    #pragma unroll
    for (int g = 0; g < 3; g++)
        #pragma unroll
        for (int p = 0; p < 2; p++) wmma::fill_fragment(acc[g][p], 0.f);

    for (int k0 = 0; k0 < HP; k0 += 16) {
        __syncthreads();
        {   // stage hprev 64x16
            int m = tid >> 2, kq = (tid & 3) * 4;
            #pragma unroll
            for (int q = 0; q < 4; q++) {
                int k = k0 + kq + q;
                sH[m * 20 + kq + q] = (k < HP) ? hprev[(size_t)(b0 + m) * HP + k] : 0.f;
            }
        }
        {   // stage W for 3 gates: 16x64 each (coalesced along k)
            int k = tid & 15, ng = tid >> 4;
            int kk = k0 + k;
            #pragma unroll
            for (int g = 0; g < 3; g++)
                #pragma unroll
                for (int q = 0; q < 4; q++) {
                    int j = ng * 4 + q;
                    int jj = j0 + j;
                    float v = (kk < HH && jj < HH) ? W[(size_t)(g * HH + jj) * HH + kk] : 0.f;
                    sB[(g * 16 + k) * 68 + j] = v;
                }
        }
        __syncthreads();
        #pragma unroll
        for (int kk = 0; kk < 16; kk += 8) {
            wmma::fragment<wmma::matrix_a, 16, 16, 8, wmma::precision::tf32, wmma::row_major> af;
            wmma::load_matrix_sync(af, &sH[(wm * 16) * 20 + kk], 20);
            #pragma unroll
            for (int e = 0; e < af.num_elements; e++)
                af.x[e] = wmma::__float_to_tf32(af.x[e]);
            #pragma unroll
            for (int g = 0; g < 3; g++)
                #pragma unroll
                for (int p = 0; p < 2; p++) {
                    wmma::fragment<wmma::matrix_b, 16, 16, 8, wmma::precision::tf32, wmma::row_major> bfr;
                    wmma::load_matrix_sync(bfr, &sB[(g * 16 + kk) * 68 + wn * 32 + p * 16], 68);
                    #pragma unroll
                    for (int e = 0; e < bfr.num_elements; e++)
                        bfr.x[e] = wmma::__float_to_tf32(bfr.x[e]);
                    wmma::mma_sync(acc[g][p], af, bfr, acc[g][p]);
                }
        }
    }

    // epilogue: warp-local; gates for the same (row, j) live in the same warp
    float* cw = &sC[warp * 3 * 256];
    #pragma unroll
    for (int p = 0; p < 2; p++) {
        #pragma unroll
        for (int g = 0; g < 3; g++)
            wmma::store_matrix_sync(cw + g * 256, acc[g][p], 16, wmma::mem_row_major);
        __syncwarp();
        #pragma unroll
        for (int q = 0; q < 8; q++) {
            int e = lane * 8 + q;
            int row = e >> 4, col = e & 15;
            int j = j0 + wn * 32 + p * 16 + col;
            if (j < HH) {
                int b = b0 + wm * 16 + row;
                size_t xb = ((size_t)b * TT + t) * (size_t)G3;
                float cr = cw[0 * 256 + e], cz = cw[1 * 256 + e], cn = cw[2 * 256 + e];
                float r = 1.f / (1.f + expf(-(xg[xb + j] + cr + bhh[j])));
                float z = 1.f / (1.f + expf(-(xg[xb + HH + j] + cz + bhh[HH + j])));
                float nn = tanhf(xg[xb + 2 * HH + j] + r * (cn + bhh[2 * HH + j]));
                hout[(size_t)b * HP + j] = (1.f - z) * nn + z * hprev[(size_t)b * HP + j];
            }
        }
        __syncwarp();
    }
}

// =================== 3. word attention scores (tf32 wmma + fused tanh/proj) ===================
// per block: fixed t, 64 batch rows; loops 8 n-tiles of 64 (N=460 pad 512); K = 464 = 232+232.
__global__ __launch_bounds__(256) void word_score_wmma(
    const float* __restrict__ Ww, const float* __restrict__ bw, const float* __restrict__ pw)
{
    __shared__ float sA[64 * 20];
    __shared__ float sB[16 * 68];
    __shared__ float sC[8 * 256];
    __shared__ float srow[64];

    const int t = blockIdx.x;
    const int b0 = blockIdx.y * 64;
    const int tid = threadIdx.x;
    const int warp = tid >> 5, lane = tid & 31;
    const int wm = warp >> 1, wn = warp & 1;

    const float* hf = g_hf + (size_t)(t + 1) * BDIM * HP;
    const float* hr = g_hr + (size_t)t * BDIM * HP;

    if (tid < 64) srow[tid] = 0.f;

    for (int n0 = 0; n0 < 512; n0 += 64) {
        wmma::fragment<wmma::accumulator, 16, 16, 8, float> acc[2];
        #pragma unroll
        for (int p = 0; p < 2; p++) wmma::fill_fragment(acc[p], 0.f);

        for (int k0 = 0; k0 < 464; k0 += 16) {
            __syncthreads();
            {   // stage A 64x16 from concat(hf, hr); pad cols are zero already
                int m = tid >> 2, kq = (tid & 3) * 4;
                #pragma unroll
                for (int q = 0; q < 4; q++) {
                    int k = k0 + kq + q;
                    float v = (k < HP) ? hf[(size_t)(b0 + m) * HP + k]
                                       : hr[(size_t)(b0 + m) * HP + (k - HP)];
                    sA[m * 20 + kq + q] = v;
                }
            }
            {   // stage B 16x64 from W_word with padded-k mapping
                int k = tid & 15, ng = tid >> 4;
                int kk = k0 + k;
                int ksrc = (kk < HH) ? kk : (kk >= HP && kk < HP + HH) ? (kk - 2) : -1;
                #pragma unroll
                for (int q = 0; q < 4; q++) {
                    int n = ng * 4 + q;
                    int j = n0 + n;
                    float v = (ksrc >= 0 && j < H2) ? Ww[(size_t)ksrc * H2 + j] : 0.f;
                    sB[k * 68 + n] = v;
                }
            }
            __syncthreads();
            #pragma unroll
            for (int kk = 0; kk < 16; kk += 8) {
                wmma::fragment<wmma::matrix_a, 16, 16, 8, wmma::precision::tf32, wmma::row_major> af;
                wmma::load_matrix_sync(af, &sA[(wm * 16) * 20 + kk], 20);
                #pragma unroll
                for (int e = 0; e < af.num_elements; e++)
                    af.x[e] = wmma::__float_to_tf32(af.x[e]);
                #pragma unroll
                for (int p = 0; p < 2; p++) {
                    wmma::fragment<wmma::matrix_b, 16, 16, 8, wmma::precision::tf32, wmma::row_major> bfr;
                    wmma::load_matrix_sync(bfr, &sB[kk * 68 + wn * 32 + p * 16], 68);
                    #pragma unroll
                    for (int e = 0; e < bfr.num_elements; e++)
                        bfr.x[e] = wmma::__float_to_tf32(bfr.x[e]);
                    wmma::mma_sync(acc[p], af, bfr, acc[p]);
                }
            }
        }
        // fused epilogue: tanh(c + b) * proj, row-sum
        float* cw = &sC[warp * 256];
        #pragma unroll
        for (int p = 0; p < 2; p++) {
            wmma::store_matrix_sync(cw, acc[p], 16, wmma::mem_row_major);
            __syncwarp();
            float part = 0.f;
            #pragma unroll
            for (int q = 0; q < 8; q++) {
                int e = lane * 8 + q;
                int col = e & 15;
                int j = n0 + wn * 32 + p * 16 + col;
                if (j < H2) part += tanhf(cw[e] + bw[j]) * pw[j];
            }
            atomicAdd(&srow[wm * 16 + (lane >> 1)], part);
            __syncwarp();
        }
    }
    __syncthreads();
    if (tid < 64) g_scores[(size_t)(b0 + tid) * TT + t] = srow[tid];
}

// =================== 4. softmax over t + weighted sum -> word_vec ===================
__global__ void word_attn()
{
    __shared__ float alpha[TT];
    __shared__ float red[2];
    const int b = blockIdx.x;
    const int tid = threadIdx.x;
    if (tid < TT) alpha[tid] = g_scores[(size_t)b * TT + tid];
    __syncthreads();
    if (tid == 0) {
        float m = -1e30f;
        for (int t2 = 0; t2 < TT; t2++) m = fmaxf(m, alpha[t2]);
        red[0] = m;
    }
    __syncthreads();
    if (tid < TT) alpha[tid] = expf(alpha[tid] - red[0]);
    __syncthreads();
    if (tid == 0) {
        float ssum = 0.f;
        for (int t2 = 0; t2 < TT; t2++) ssum += alpha[t2];
        red[1] = 1.f / ssum;
    }
    __syncthreads();
    if (tid < TT) alpha[tid] *= red[1];
    __syncthreads();
    const size_t stride = (size_t)BDIM * HP;
    for (int hcol = tid; hcol < H2; hcol += 256) {
        const float* base = (hcol < HH)
            ? (g_hf + stride + (size_t)b * HP + hcol)            // slab t+1
            : (g_hr + (size_t)b * HP + (hcol - HH));             // slab t
        float acc = 0.f;
        #pragma unroll 4
        for (int t2 = 0; t2 < TT; t2++) acc += alpha[t2] * base[(size_t)t2 * stride];
        g_wordvec[(size_t)b * H2 + hcol] = acc;
    }
}

// =================== 5. zero output ===================
__global__ void zero_out(float* __restrict__ out, int n)
{
    int i = blockIdx.x * 256 + threadIdx.x;
    if (i < n) out[i] = 0.f;
}

// =================== 6. sentence attention + FC + scatter ===================
__global__ void sent_kernel(const float* __restrict__ Wsent, const float* __restrict__ bsent,
                            const float* __restrict__ psent, const float* __restrict__ fcW,
                            const float* __restrict__ fcb, const int* __restrict__ pairs,
                            float* __restrict__ out)
{
    __shared__ float wvs[MS][H2];
    __shared__ float score[MS];
    __shared__ float beta[MS];
    __shared__ float sv[H2];
    const int nb = blockIdx.x;
    const int tid = threadIdx.x;

    for (int i = tid; i < MS * H2; i += 256)
        wvs[i / H2][i % H2] = g_wordvec[(size_t)nb * MS * H2 + i];
    if (tid < MS) score[tid] = 0.f;
    __syncthreads();

    for (int j = tid; j < H2; j += 256) {
        float acc[MS];
        #pragma unroll
        for (int s = 0; s < MS; s++) acc[s] = 0.f;
        for (int k = 0; k < H2; k++) {
            float w = Wsent[(size_t)k * H2 + j];
            #pragma unroll
            for (int s = 0; s < MS; s++) acc[s] += wvs[s][k] * w;
        }
        float bb = bsent[j], pp = psent[j];
        #pragma unroll
        for (int s = 0; s < MS; s++) atomicAdd(&score[s], tanhf(acc[s] + bb) * pp);
    }
    __syncthreads();
    if (tid == 0) {
        float m = -1e30f;
        for (int s = 0; s < MS; s++) m = fmaxf(m, score[s]);
        float sum = 0.f;
        for (int s = 0; s < MS; s++) { beta[s] = expf(score[s] - m); sum += beta[s]; }
        float inv = 1.f / sum;
        for (int s = 0; s < MS; s++) beta[s] *= inv;
    }
    __syncthreads();
    for (int hcol = tid; hcol < H2; hcol += 256) {
        float acc = 0.f;
        #pragma unroll
        for (int s = 0; s < MS; s++) acc += beta[s] * wvs[s][hcol];
        sv[hcol] = acc;
    }
    __syncthreads();
    if (tid < NOUT) {
        int o = tid;
        float acc = fcb[o];
        for (int k = 0; k < H2; k++) acc += sv[k] * fcW[(size_t)o * H2 + k];
        int p0 = pairs[nb * 3 + 0];
        int p1 = pairs[nb * 3 + 1];
        int p2 = pairs[nb * 3 + 2];
        out[(((size_t)p0 * NENT + p1) * NENT + p2) * NOUT + o] = acc;
    }
}

// =================== launcher ===================
extern "C" void kernel_launch(void* const* d_in, const int* in_sizes, int n_in,
                              void* d_out, int out_size)
{
    const float* bag       = (const float*)d_in[0];
    const float* W_ih_f    = (const float*)d_in[1];
    const float* W_hh_f    = (const float*)d_in[2];
    const float* b_ih_f    = (const float*)d_in[3];
    const float* b_hh_f    = (const float*)d_in[4];
    const float* W_ih_r    = (const float*)d_in[5];
    const float* W_hh_r    = (const float*)d_in[6];
    const float* b_ih_r    = (const float*)d_in[7];
    const float* b_hh_r    = (const float*)d_in[8];
    const float* W_word    = (const float*)d_in[9];
    const float* b_word    = (const float*)d_in[10];
    const float* proj_word = (const float*)d_in[11];
    const float* W_sent    = (const float*)d_in[12];
    const float* b_sent    = (const float*)d_in[13];
    const float* proj_sent = (const float*)d_in[14];
    const float* fc_W      = (const float*)d_in[15];
    const float* fc_b      = (const float*)d_in[16];
    const int*   pairs     = (const int*)d_in[17];
    float* out = (float*)d_out;

    // 1. input GEMMs (both directions, b_ih fused), tf32 tensor cores
    dim3 gI((G3 + 63) / 64, M_TOT / 128, 2);
    input_gemm_wmma<<<gI, 256>>>(bag, W_ih_f, b_ih_f, W_ih_r, b_ih_r);

    // 2. 64 sequential GRU steps (fwd + rev concurrent per launch), tf32 tensor cores
    dim3 gS((HH + 63) / 64, BDIM / 64, 2);
    for (int s = 0; s < TT; s++)
        gru_step_wmma<<<gS, 256>>>(W_hh_f, b_hh_f, W_hh_r, b_hh_r, s);

    // 3. word attention scores, tf32 tensor cores + fused tanh/proj epilogue
    dim3 gW(TT, BDIM / 64);
    word_score_wmma<<<gW, 256>>>(W_word, b_word, proj_word);

    // 4. softmax over t + word_vec
    word_attn<<<BDIM, 256>>>();

    // 5. zero output buffer
    int n_out = NDOCS * NENT * NENT * NOUT;
    zero_out<<<(n_out + 255) / 256, 256>>>(out, n_out);

    // 6. sentence attention + FC + scatter
    sent_kernel<<<NBAG, 256>>>(W_sent, b_sent, proj_sent, fc_W, fc_b, pairs, out);
}

// round 6
// speedup vs baseline: 1.1041x; 1.1041x over previous
#include <cuda_runtime.h>
#include <mma.h>
#include <math.h>

using namespace nvcuda;

#define NBAG 512
#define MS 8
#define TT 64
#define BDIM 4096          // NBAG*MS
#define INDIM 360
#define HH 230
#define H2 460
#define G3 690
#define NOUT 53
#define NDOCS 32
#define NENT 8
#define HP 232             // padded H (mult of 8)
#define M_TOT (BDIM * TT)  // 262144

// ------------------- scratch (device globals; zero-initialized at module load) -------------------
__device__ float g_xg[2ull * M_TOT * G3];                 // [dir][m=b*T+t][690]
// slab-indexed hidden states. fwd: h_t lives at slab t+1 (slab 0 = zeros, never written).
// rev: h_t lives at slab t (slab TT = zeros, never written). pad cols 230,231 never written.
__device__ float g_hf[(size_t)(TT + 1) * BDIM * HP];
__device__ float g_hr[(size_t)(TT + 1) * BDIM * HP];
__device__ float g_scores[(size_t)BDIM * TT];             // [b][t]
__device__ float g_wordvec[(size_t)BDIM * H2];            // [b][460]

#define TF32(x) wmma::__float_to_tf32(x)

// =================== 1. input GEMM (tf32 wmma): xg = bag @ W_ih^T + b_ih ===================
// M=262144, N=690 (pad 704), K=360.  BM=128, BN=64, BK=16, 8 warps (4m x 2n).
// smem holds pre-rounded tf32 values; no fragment conversions. Register-prefetch k pipeline.
__global__ __launch_bounds__(256) void input_gemm_wmma(
    const float* __restrict__ A,
    const float* __restrict__ Wf, const float* __restrict__ bf_,
    const float* __restrict__ Wr, const float* __restrict__ br_)
{
    __shared__ float sA[128 * 20];   // [m][k], ld 20
    __shared__ float sB[16 * 68];    // [k][n], ld 68
    __shared__ float sC[128 * 64];   // epilogue staging

    const int dir = blockIdx.z;
    const float* W    = dir ? Wr : Wf;
    const float* bias = dir ? br_ : bf_;
    float* C = g_xg + (size_t)dir * M_TOT * G3;

    const int n0 = blockIdx.x * 64;
    const int m0 = blockIdx.y * 128;
    const int tid = threadIdx.x;
    const int warp = tid >> 5;
    const int wm = warp >> 1, wn = warp & 1;

    wmma::fragment<wmma::accumulator, 16, 16, 8, float> acc[2][2];
    #pragma unroll
    for (int i = 0; i < 2; i++)
        #pragma unroll
        for (int j = 0; j < 2; j++) wmma::fill_fragment(acc[i][j], 0.f);

    // staging thread mapping
    const int am = tid >> 1, akoff = (tid & 1) * 8;   // A: row, 8 k's
    const float* ap = A + (size_t)(m0 + am) * INDIM;
    const int bk = tid & 15, bng = tid >> 4;          // B: k lane, 4 n's
    const int bn_base = n0 + bng * 4;

    float aReg[8], bReg[4];
    const int NIT = (INDIM + 15) / 16;  // 23

    {   // preload iter 0
        #pragma unroll
        for (int q = 0; q < 8; q++) {
            int k = akoff + q;
            aReg[q] = (k < INDIM) ? ap[k] : 0.f;
        }
        #pragma unroll
        for (int q = 0; q < 4; q++) {
            int nn = bn_base + q;
            bReg[q] = (bk < INDIM && nn < G3) ? W[(size_t)nn * INDIM + bk] : 0.f;
        }
    }

    for (int it = 0; it < NIT; ++it) {
        __syncthreads();
        #pragma unroll
        for (int q = 0; q < 8; q++) sA[am * 20 + akoff + q] = TF32(aReg[q]);
        #pragma unroll
        for (int q = 0; q < 4; q++) sB[bk * 68 + bng * 4 + q] = TF32(bReg[q]);
        __syncthreads();
        if (it + 1 < NIT) {   // prefetch next k-tile while MMAs run
            int kbase = (it + 1) * 16;
            #pragma unroll
            for (int q = 0; q < 8; q++) {
                int k = kbase + akoff + q;
                aReg[q] = (k < INDIM) ? ap[k] : 0.f;
            }
            int kk = kbase + bk;
            #pragma unroll
            for (int q = 0; q < 4; q++) {
                int nn = bn_base + q;
                bReg[q] = (kk < INDIM && nn < G3) ? W[(size_t)nn * INDIM + kk] : 0.f;
            }
        }
        #pragma unroll
        for (int kk = 0; kk < 16; kk += 8) {
            wmma::fragment<wmma::matrix_b, 16, 16, 8, wmma::precision::tf32, wmma::row_major> bfr[2];
            #pragma unroll
            for (int ni = 0; ni < 2; ni++)
                wmma::load_matrix_sync(bfr[ni], &sB[kk * 68 + wn * 32 + ni * 16], 68);
            #pragma unroll
            for (int mi = 0; mi < 2; mi++) {
                wmma::fragment<wmma::matrix_a, 16, 16, 8, wmma::precision::tf32, wmma::row_major> af;
                wmma::load_matrix_sync(af, &sA[(wm * 32 + mi * 16) * 20 + kk], 20);
                #pragma unroll
                for (int ni = 0; ni < 2; ni++)
                    wmma::mma_sync(acc[mi][ni], af, bfr[ni], acc[mi][ni]);
            }
        }
    }
    __syncthreads();
    #pragma unroll
    for (int mi = 0; mi < 2; mi++)
        #pragma unroll
        for (int ni = 0; ni < 2; ni++)
            wmma::store_matrix_sync(&sC[(wm * 32 + mi * 16) * 64 + wn * 32 + ni * 16],
                                    acc[mi][ni], 64, wmma::mem_row_major);
    __syncthreads();
    {   // write out: warp lanes cover consecutive cols -> coalesced
        int col = tid & 63;
        int r0 = tid >> 6;
        int n = n0 + col;
        if (n < G3) {
            float bv = bias[n];
            #pragma unroll 8
            for (int i = 0; i < 32; i++) {
                int m = r0 * 32 + i;
                C[(size_t)(m0 + m) * G3 + n] = sC[m * 64 + col] + bv;
            }
        }
    }
}

// =================== 2. GRU step (tf32 wmma, 3 gates fused) ===================
// per block: 64 batch rows x 64 j's, all 3 gate GEMMs. K = 232 (padded).
__global__ __launch_bounds__(256) void gru_step_wmma(
    const float* __restrict__ Whhf, const float* __restrict__ bhhf,
    const float* __restrict__ Whhr, const float* __restrict__ bhhr,
    int s)
{
    __shared__ float sH[64 * 20];        // [m][k], ld 20
    __shared__ float sB[3 * 16 * 68];    // [g][k][j], ld 68
    __shared__ float sC[8 * 3 * 256];    // per-warp, per-gate 16x16

    const int dir = blockIdx.z;
    const int t = dir ? (TT - 1 - s) : s;
    const float* W   = dir ? Whhr : Whhf;
    const float* bhh = dir ? bhhr : bhhf;
    const float* xg = g_xg + (size_t)dir * M_TOT * G3;
    float* hbase = dir ? g_hr : g_hf;
    const int slab_prev = dir ? (t + 1) : t;
    const int slab_out  = dir ? t : (t + 1);
    const float* hprev = hbase + (size_t)slab_prev * BDIM * HP;
    float* hout = hbase + (size_t)slab_out * BDIM * HP;

    const int j0 = blockIdx.x * 64;
    const int b0 = blockIdx.y * 64;
    const int tid = threadIdx.x;
    const int warp = tid >> 5, lane = tid & 31;
    const int wm = warp >> 1, wn = warp & 1;

    wmma::fragment<wmma::accumulator, 16, 16, 8, float> acc[3][2];
    #pragma unroll
    for (int g = 0; g < 3; g++)
        #pragma unroll
        for (int p = 0; p < 2; p++) wmma::fill_fragment(acc[g][p], 0.f);

    // staging thread mapping
    const int hm = tid >> 2, hkq = (tid & 3) * 4;     // H: row, 4 k's
    const float* hp_row = hprev + (size_t)(b0 + hm) * HP;
    const int wk = tid & 15, wng = tid >> 4;          // W: k lane, 4 j's per gate
    const int wj_base = j0 + wng * 4;

    float hReg[4], wReg[3][4];
    const int NIT = (HP + 15) / 16;  // 15 (last tile k 224..239, guarded)

    {   // preload iter 0
        #pragma unroll
        for (int q = 0; q < 4; q++) {
            int k = hkq + q;
            hReg[q] = (k < HP) ? hp_row[k] : 0.f;
        }
        #pragma unroll
        for (int g = 0; g < 3; g++)
            #pragma unroll
            for (int q = 0; q < 4; q++) {
                int jj = wj_base + q;
                wReg[g][q] = (wk < HH && jj < HH) ? W[(size_t)(g * HH + jj) * HH + wk] : 0.f;
            }
    }

    for (int it = 0; it < NIT; ++it) {
        __syncthreads();
        #pragma unroll
        for (int q = 0; q < 4; q++) sH[hm * 20 + hkq + q] = TF32(hReg[q]);
        #pragma unroll
        for (int g = 0; g < 3; g++)
            #pragma unroll
            for (int q = 0; q < 4; q++)
                sB[(g * 16 + wk) * 68 + wng * 4 + q] = TF32(wReg[g][q]);
        __syncthreads();
        if (it + 1 < NIT) {   // prefetch next k-tile
            int kbase = (it + 1) * 16;
            #pragma unroll
            for (int q = 0; q < 4; q++) {
                int k = kbase + hkq + q;
                hReg[q] = (k < HP) ? hp_row[k] : 0.f;
            }
            int kk = kbase + wk;
            #pragma unroll
            for (int g = 0; g < 3; g++)
                #pragma unroll
                for (int q = 0; q < 4; q++) {
                    int jj = wj_base + q;
                    wReg[g][q] = (kk < HH && jj < HH) ? W[(size_t)(g * HH + jj) * HH + kk] : 0.f;
                }
        }
        #pragma unroll
        for (int kk = 0; kk < 16; kk += 8) {
            wmma::fragment<wmma::matrix_a, 16, 16, 8, wmma::precision::tf32, wmma::row_major> af;
            wmma::load_matrix_sync(af, &sH[(wm * 16) * 20 + kk], 20);
            #pragma unroll
            for (int g = 0; g < 3; g++)
                #pragma unroll
                for (int p = 0; p < 2; p++) {
                    wmma::fragment<wmma::matrix_b, 16, 16, 8, wmma::precision::tf32, wmma::row_major> bfr;
                    wmma::load_matrix_sync(bfr, &sB[(g * 16 + kk) * 68 + wn * 32 + p * 16], 68);
                    wmma::mma_sync(acc[g][p], af, bfr, acc[g][p]);
                }
        }
    }

    // epilogue: warp-local; gates for the same (row, j) live in the same warp
    float* cw = &sC[warp * 3 * 256];
    #pragma unroll
    for (int p = 0; p < 2; p++) {
        #pragma unroll
        for (int g = 0; g < 3; g++)
            wmma::store_matrix_sync(cw + g * 256, acc[g][p], 16, wmma::mem_row_major);
        __syncwarp();
        #pragma unroll
        for (int q = 0; q < 8; q++) {
            int e = lane * 8 + q;
            int row = e >> 4, col = e & 15;
            int j = j0 + wn * 32 + p * 16 + col;
            if (j < HH) {
                int b = b0 + wm * 16 + row;
                size_t xb = ((size_t)b * TT + t) * (size_t)G3;
                float cr = cw[0 * 256 + e], cz = cw[1 * 256 + e], cn = cw[2 * 256 + e];
                float r = 1.f / (1.f + expf(-(xg[xb + j] + cr + bhh[j])));
                float z = 1.f / (1.f + expf(-(xg[xb + HH + j] + cz + bhh[HH + j])));
                float nn = tanhf(xg[xb + 2 * HH + j] + r * (cn + bhh[2 * HH + j]));
                hout[(size_t)b * HP + j] = (1.f - z) * nn + z * hprev[(size_t)b * HP + j];
            }
        }
        __syncwarp();
    }
}

// =================== 3. word attention scores (tf32 wmma + fused tanh/proj) ===================
// per block: fixed t, 64 batch rows; loops 8 n-tiles of 64 (N=460 pad 512); K = 464 = 232+232.
__global__ __launch_bounds__(256) void word_score_wmma(
    const float* __restrict__ Ww, const float* __restrict__ bw, const float* __restrict__ pw)
{
    __shared__ float sA[64 * 20];
    __shared__ float sB[16 * 68];
    __shared__ float sC[8 * 256];
    __shared__ float srow[64];

    const int t = blockIdx.x;
    const int b0 = blockIdx.y * 64;
    const int tid = threadIdx.x;
    const int warp = tid >> 5, lane = tid & 31;
    const int wm = warp >> 1, wn = warp & 1;

    const float* hf = g_hf + (size_t)(t + 1) * BDIM * HP;
    const float* hr = g_hr + (size_t)t * BDIM * HP;

    if (tid < 64) srow[tid] = 0.f;

    // staging thread mapping
    const int am = tid >> 2, akq = (tid & 3) * 4;     // A: row, 4 k's
    const float* hf_row = hf + (size_t)(b0 + am) * HP;
    const float* hr_row = hr + (size_t)(b0 + am) * HP;
    const int bk = tid & 15, bng = tid >> 4;          // B: k lane, 4 n's
    const int NIT = 464 / 16;  // 29

    float aReg[4], bReg[4];

    for (int n0 = 0; n0 < 512; n0 += 64) {
        wmma::fragment<wmma::accumulator, 16, 16, 8, float> acc[2];
        #pragma unroll
        for (int p = 0; p < 2; p++) wmma::fill_fragment(acc[p], 0.f);

        {   // preload iter 0 of this n-chunk (k = bk in 0..15, always valid)
            #pragma unroll
            for (int q = 0; q < 4; q++) {
                int k = akq + q;
                aReg[q] = (k < HP) ? hf_row[k] : hr_row[k - HP];
            }
            #pragma unroll
            for (int q = 0; q < 4; q++) {
                int j = n0 + bng * 4 + q;
                bReg[q] = (j < H2) ? Ww[(size_t)bk * H2 + j] : 0.f;
            }
        }

        for (int it = 0; it < NIT; ++it) {
            __syncthreads();
            #pragma unroll
            for (int q = 0; q < 4; q++) sA[am * 20 + akq + q] = TF32(aReg[q]);
            #pragma unroll
            for (int q = 0; q < 4; q++) sB[bk * 68 + bng * 4 + q] = TF32(bReg[q]);
            __syncthreads();
            if (it + 1 < NIT) {
                int kbase = (it + 1) * 16;
                #pragma unroll
                for (int q = 0; q < 4; q++) {
                    int k = kbase + akq + q;
                    aReg[q] = (k < HP) ? hf_row[k] : hr_row[k - HP];
                }
                int kk = kbase + bk;
                int ksrc = (kk < HH) ? kk : (kk >= HP && kk < HP + HH) ? (kk - 2) : -1;
                #pragma unroll
                for (int q = 0; q < 4; q++) {
                    int j = n0 + bng * 4 + q;
                    bReg[q] = (ksrc >= 0 && j < H2) ? Ww[(size_t)ksrc * H2 + j] : 0.f;
                }
            }
            #pragma unroll
            for (int kk = 0; kk < 16; kk += 8) {
                wmma::fragment<wmma::matrix_a, 16, 16, 8, wmma::precision::tf32, wmma::row_major> af;
                wmma::load_matrix_sync(af, &sA[(wm * 16) * 20 + kk], 20);
                #pragma unroll
                for (int p = 0; p < 2; p++) {
                    wmma::fragment<wmma::matrix_b, 16, 16, 8, wmma::precision::tf32, wmma::row_major> bfr;
                    wmma::load_matrix_sync(bfr, &sB[kk * 68 + wn * 32 + p * 16], 68);
                    wmma::mma_sync(acc[p], af, bfr, acc[p]);
                }
            }
        }
        // fused epilogue: tanh(c + b) * proj, row-sum
        float* cw = &sC[warp * 256];
        #pragma unroll
        for (int p = 0; p < 2; p++) {
            wmma::store_matrix_sync(cw, acc[p], 16, wmma::mem_row_major);
            __syncwarp();
            float part = 0.f;
            #pragma unroll
            for (int q = 0; q < 8; q++) {
                int e = lane * 8 + q;
                int col = e & 15;
                int j = n0 + wn * 32 + p * 16 + col;
                if (j < H2) part += tanhf(cw[e] + bw[j]) * pw[j];
            }
            atomicAdd(&srow[wm * 16 + (lane >> 1)], part);
            __syncwarp();
        }
    }
    __syncthreads();
    if (tid < 64) g_scores[(size_t)(b0 + tid) * TT + t] = srow[tid];
}

// =================== 4. softmax over t + weighted sum -> word_vec ===================
__global__ void word_attn()
{
    __shared__ float alpha[TT];
    __shared__ float red[2];
    const int b = blockIdx.x;
    const int tid = threadIdx.x;
    if (tid < TT) alpha[tid] = g_scores[(size_t)b * TT + tid];
    __syncthreads();
    if (tid == 0) {
        float m = -1e30f;
        for (int t2 = 0; t2 < TT; t2++) m = fmaxf(m, alpha[t2]);
        red[0] = m;
    }
    __syncthreads();
    if (tid < TT) alpha[tid] = expf(alpha[tid] - red[0]);
    __syncthreads();
    if (tid == 0) {
        float ssum = 0.f;
        for (int t2 = 0; t2 < TT; t2++) ssum += alpha[t2];
        red[1] = 1.f / ssum;
    }
    __syncthreads();
    if (tid < TT) alpha[tid] *= red[1];
    __syncthreads();
    const size_t stride = (size_t)BDIM * HP;
    for (int hcol = tid; hcol < H2; hcol += 256) {
        const float* base = (hcol < HH)
            ? (g_hf + stride + (size_t)b * HP + hcol)            // slab t+1
            : (g_hr + (size_t)b * HP + (hcol - HH));             // slab t
        float acc = 0.f;
        #pragma unroll 4
        for (int t2 = 0; t2 < TT; t2++) acc += alpha[t2] * base[(size_t)t2 * stride];
        g_wordvec[(size_t)b * H2 + hcol] = acc;
    }
}

// =================== 5. zero output ===================
__global__ void zero_out(float* __restrict__ out, int n)
{
    int i = blockIdx.x * 256 + threadIdx.x;
    if (i < n) out[i] = 0.f;
}

// =================== 6. sentence attention + FC + scatter ===================
__global__ void sent_kernel(const float* __restrict__ Wsent, const float* __restrict__ bsent,
                            const float* __restrict__ psent, const float* __restrict__ fcW,
                            const float* __restrict__ fcb, const int* __restrict__ pairs,
                            float* __restrict__ out)
{
    __shared__ float wvs[MS][H2];
    __shared__ float score[MS];
    __shared__ float beta[MS];
    __shared__ float sv[H2];
    const int nb = blockIdx.x;
    const int tid = threadIdx.x;

    for (int i = tid; i < MS * H2; i += 256)
        wvs[i / H2][i % H2] = g_wordvec[(size_t)nb * MS * H2 + i];
    if (tid < MS) score[tid] = 0.f;
    __syncthreads();

    for (int j = tid; j < H2; j += 256) {
        float acc[MS];
        #pragma unroll
        for (int s = 0; s < MS; s++) acc[s] = 0.f;
        for (int k = 0; k < H2; k++) {
            float w = Wsent[(size_t)k * H2 + j];
            #pragma unroll
            for (int s = 0; s < MS; s++) acc[s] += wvs[s][k] * w;
        }
        float bb = bsent[j], pp = psent[j];
        #pragma unroll
        for (int s = 0; s < MS; s++) atomicAdd(&score[s], tanhf(acc[s] + bb) * pp);
    }
    __syncthreads();
    if (tid == 0) {
        float m = -1e30f;
        for (int s = 0; s < MS; s++) m = fmaxf(m, score[s]);
        float sum = 0.f;
        for (int s = 0; s < MS; s++) { beta[s] = expf(score[s] - m); sum += beta[s]; }
        float inv = 1.f / sum;
        for (int s = 0; s < MS; s++) beta[s] *= inv;
    }
    __syncthreads();
    for (int hcol = tid; hcol < H2; hcol += 256) {
        float acc = 0.f;
        #pragma unroll
        for (int s = 0; s < MS; s++) acc += beta[s] * wvs[s][hcol];
        sv[hcol] = acc;
    }
    __syncthreads();
    if (tid < NOUT) {
        int o = tid;
        float acc = fcb[o];
        for (int k = 0; k < H2; k++) acc += sv[k] * fcW[(size_t)o * H2 + k];
        int p0 = pairs[nb * 3 + 0];
        int p1 = pairs[nb * 3 + 1];
        int p2 = pairs[nb * 3 + 2];
        out[(((size_t)p0 * NENT + p1) * NENT + p2) * NOUT + o] = acc;
    }
}

// =================== launcher ===================
extern "C" void kernel_launch(void* const* d_in, const int* in_sizes, int n_in,
                              void* d_out, int out_size)
{
    const float* bag       = (const float*)d_in[0];
    const float* W_ih_f    = (const float*)d_in[1];
    const float* W_hh_f    = (const float*)d_in[2];
    const float* b_ih_f    = (const float*)d_in[3];
    const float* b_hh_f    = (const float*)d_in[4];
    const float* W_ih_r    = (const float*)d_in[5];
    const float* W_hh_r    = (const float*)d_in[6];
    const float* b_ih_r    = (const float*)d_in[7];
    const float* b_hh_r    = (const float*)d_in[8];
    const float* W_word    = (const float*)d_in[9];
    const float* b_word    = (const float*)d_in[10];
    const float* proj_word = (const float*)d_in[11];
    const float* W_sent    = (const float*)d_in[12];
    const float* b_sent    = (const float*)d_in[13];
    const float* proj_sent = (const float*)d_in[14];
    const float* fc_W      = (const float*)d_in[15];
    const float* fc_b      = (const float*)d_in[16];
    const int*   pairs     = (const int*)d_in[17];
    float* out = (float*)d_out;

    // 1. input GEMMs (both directions, b_ih fused), tf32 tensor cores
    dim3 gI((G3 + 63) / 64, M_TOT / 128, 2);
    input_gemm_wmma<<<gI, 256>>>(bag, W_ih_f, b_ih_f, W_ih_r, b_ih_r);

    // 2. 64 sequential GRU steps (fwd + rev concurrent per launch), tf32 tensor cores
    dim3 gS((HH + 63) / 64, BDIM / 64, 2);
    for (int s = 0; s < TT; s++)
        gru_step_wmma<<<gS, 256>>>(W_hh_f, b_hh_f, W_hh_r, b_hh_r, s);

    // 3. word attention scores, tf32 tensor cores + fused tanh/proj epilogue
    dim3 gW(TT, BDIM / 64);
    word_score_wmma<<<gW, 256>>>(W_word, b_word, proj_word);

    // 4. softmax over t + word_vec
    word_attn<<<BDIM, 256>>>();

    // 5. zero output buffer
    int n_out = NDOCS * NENT * NENT * NOUT;
    zero_out<<<(n_out + 255) / 256, 256>>>(out, n_out);

    // 6. sentence attention + FC + scatter
    sent_kernel<<<NBAG, 256>>>(W_sent, b_sent, proj_sent, fc_W, fc_b, pairs, out);
}

// round 7
// speedup vs baseline: 1.1073x; 1.0029x over previous
#include <cuda_runtime.h>
#include <mma.h>
#include <math.h>

using namespace nvcuda;

#define NBAG 512
#define MS 8
#define TT 64
#define BDIM 4096          // NBAG*MS
#define INDIM 360
#define HH 230
#define H2 460
#define G3 690
#define G3P 768            // padded xg row stride (multiple of 128)
#define NOUT 53
#define NDOCS 32
#define NENT 8
#define HP 232             // padded H (mult of 8)
#define M_TOT (BDIM * TT)  // 262144

// ------------------- scratch (device globals; zero-initialized at module load) -------------------
__device__ float g_xg[2ull * M_TOT * G3P];                // [dir][m=b*T+t][768]
// slab-indexed hidden states. fwd: h_t lives at slab t+1 (slab 0 = zeros, never written).
// rev: h_t lives at slab t (slab TT = zeros, never written). pad cols 230,231 never written.
__device__ float g_hf[(size_t)(TT + 1) * BDIM * HP];
__device__ float g_hr[(size_t)(TT + 1) * BDIM * HP];
__device__ float g_scores[(size_t)BDIM * TT];             // [b][t]
__device__ float g_wordvec[(size_t)BDIM * H2];            // [b][460]

#define TF32(x) wmma::__float_to_tf32(x)

// =================== 1. input GEMM (tf32 wmma): xg = bag @ W_ih^T (+bias via K-extension) ==========
// M=262144, N=768 (690 valid), K=368 (360 + bias ones-col + pad).
// BM=128, BN=128, BK=16, 8 warps as 4x2, warp tile 32x64 (8 frags). Direct frag->global epilogue.
__global__ __launch_bounds__(256) void input_gemm_wmma(
    const float* __restrict__ A,
    const float* __restrict__ Wf, const float* __restrict__ bf_,
    const float* __restrict__ Wr, const float* __restrict__ br_)
{
    __shared__ float sA[128 * 20];   // [m][k], ld 20
    __shared__ float sB[16 * 132];   // [k][n], ld 132

    const int dir = blockIdx.z;
    const float* W    = dir ? Wr : Wf;
    const float* bias = dir ? br_ : bf_;
    float* C = g_xg + (size_t)dir * M_TOT * G3P;

    const int n0 = blockIdx.x * 128;
    const int m0 = blockIdx.y * 128;
    const int tid = threadIdx.x;
    const int warp = tid >> 5;
    const int wm = warp >> 1, wn = warp & 1;   // 4 x 2

    wmma::fragment<wmma::accumulator, 16, 16, 8, float> acc[2][4];
    #pragma unroll
    for (int i = 0; i < 2; i++)
        #pragma unroll
        for (int j = 0; j < 4; j++) wmma::fill_fragment(acc[i][j], 0.f);

    // staging maps
    const int am = tid >> 1, akoff = (tid & 1) * 8;     // A: 128 rows x 16k, 8/thread
    const float* ap = A + (size_t)(m0 + am) * INDIM;
    const int bk = tid & 15, bc0 = (tid >> 4) * 8;      // B: 16k x 128n, 8/thread

    float aReg[8], bReg[8];
    const int NIT = 368 / 16;  // 23

    {   // preload iter 0 (k 0..15 < INDIM always)
        #pragma unroll
        for (int q = 0; q < 8; q++) aReg[q] = ap[akoff + q];
        #pragma unroll
        for (int q = 0; q < 8; q++) {
            int n = n0 + bc0 + q;
            bReg[q] = (n < G3) ? W[(size_t)n * INDIM + bk] : 0.f;
        }
    }

    for (int it = 0; it < NIT; ++it) {
        __syncthreads();
        #pragma unroll
        for (int q = 0; q < 8; q++) sA[am * 20 + akoff + q] = TF32(aReg[q]);
        #pragma unroll
        for (int q = 0; q < 8; q++) sB[bk * 132 + bc0 + q] = TF32(bReg[q]);
        __syncthreads();
        if (it + 1 < NIT) {   // prefetch next k-slab
            int kbase = (it + 1) * 16;
            #pragma unroll
            for (int q = 0; q < 8; q++) {
                int k = kbase + akoff + q;
                aReg[q] = (k < INDIM) ? ap[k] : (k == INDIM ? 1.0f : 0.f);
            }
            int kk = kbase + bk;
            #pragma unroll
            for (int q = 0; q < 8; q++) {
                int n = n0 + bc0 + q;
                bReg[q] = (n < G3)
                    ? (kk < INDIM ? W[(size_t)n * INDIM + kk] : (kk == INDIM ? bias[n] : 0.f))
                    : 0.f;
            }
        }
        #pragma unroll
        for (int kk = 0; kk < 16; kk += 8) {
            wmma::fragment<wmma::matrix_a, 16, 16, 8, wmma::precision::tf32, wmma::row_major> af[2];
            #pragma unroll
            for (int mi = 0; mi < 2; mi++)
                wmma::load_matrix_sync(af[mi], &sA[(wm * 32 + mi * 16) * 20 + kk], 20);
            #pragma unroll
            for (int ni = 0; ni < 4; ni++) {
                wmma::fragment<wmma::matrix_b, 16, 16, 8, wmma::precision::tf32, wmma::row_major> bfr;
                wmma::load_matrix_sync(bfr, &sB[kk * 132 + wn * 64 + ni * 16], 132);
                #pragma unroll
                for (int mi = 0; mi < 2; mi++)
                    wmma::mma_sync(acc[mi][ni], af[mi], bfr, acc[mi][ni]);
            }
        }
    }
    // direct epilogue: frags straight to global (bias already folded in)
    #pragma unroll
    for (int mi = 0; mi < 2; mi++)
        #pragma unroll
        for (int ni = 0; ni < 4; ni++)
            wmma::store_matrix_sync(
                &C[(size_t)(m0 + wm * 32 + mi * 16) * G3P + n0 + wn * 64 + ni * 16],
                acc[mi][ni], G3P, wmma::mem_row_major);
}

// =================== 2. GRU step (tf32 wmma, 3 gates fused) ===================
// per block: 128 batch rows x 64 j's, all 3 gate GEMMs. 8 warps 4x2, warp 32x32 per gate.
__global__ __launch_bounds__(256) void gru_step_wmma(
    const float* __restrict__ Whhf, const float* __restrict__ bhhf,
    const float* __restrict__ Whhr, const float* __restrict__ bhhr,
    int s)
{
    __shared__ float sH[128 * 20];       // [m][k], ld 20        10240 B
    __shared__ float sB[3 * 16 * 68];    // [g][k][j], ld 68     13056 B
    __shared__ float sC[8 * 3 * 256];    // per-warp 3-gate 16x16 staging  24576 B

    const int dir = blockIdx.z;
    const int t = dir ? (TT - 1 - s) : s;
    const float* W   = dir ? Whhr : Whhf;
    const float* bhh = dir ? bhhr : bhhf;
    const float* xg = g_xg + (size_t)dir * M_TOT * G3P;
    float* hbase = dir ? g_hr : g_hf;
    const int slab_prev = dir ? (t + 1) : t;
    const int slab_out  = dir ? t : (t + 1);
    const float* hprev = hbase + (size_t)slab_prev * BDIM * HP;
    float* hout = hbase + (size_t)slab_out * BDIM * HP;

    const int j0 = blockIdx.x * 64;
    const int b0 = blockIdx.y * 128;
    const int tid = threadIdx.x;
    const int warp = tid >> 5, lane = tid & 31;
    const int wm = warp >> 1, wn = warp & 1;   // 4 x 2: 32 rows, 32 j

    wmma::fragment<wmma::accumulator, 16, 16, 8, float> acc[3][2][2];
    #pragma unroll
    for (int g = 0; g < 3; g++)
        #pragma unroll
        for (int mi = 0; mi < 2; mi++)
            #pragma unroll
            for (int ni = 0; ni < 2; ni++) wmma::fill_fragment(acc[g][mi][ni], 0.f);

    // staging maps
    const int hm = tid >> 1, hkoff = (tid & 1) * 8;   // H: 128 rows x 16k, 8/thread
    const float* hp_row = hprev + (size_t)(b0 + hm) * HP;
    const int wk = tid & 15, wng = tid >> 4;          // W: per gate 16k x 64j, 4/thread
    const int wj0 = j0 + wng * 4;

    float hReg[8], wReg[3][4];
    const int NIT = (HP + 15) / 16;  // 15

    {   // preload iter 0 (k 0..15 valid)
        #pragma unroll
        for (int q = 0; q < 8; q++) hReg[q] = hp_row[hkoff + q];
        #pragma unroll
        for (int g = 0; g < 3; g++)
            #pragma unroll
            for (int q = 0; q < 4; q++) {
                int jj = wj0 + q;
                wReg[g][q] = (jj < HH) ? W[(size_t)(g * HH + jj) * HH + wk] : 0.f;
            }
    }

    for (int it = 0; it < NIT; ++it) {
        __syncthreads();
        #pragma unroll
        for (int q = 0; q < 8; q++) sH[hm * 20 + hkoff + q] = TF32(hReg[q]);
        #pragma unroll
        for (int g = 0; g < 3; g++)
            #pragma unroll
            for (int q = 0; q < 4; q++)
                sB[(g * 16 + wk) * 68 + wng * 4 + q] = TF32(wReg[g][q]);
        __syncthreads();
        if (it + 1 < NIT) {   // prefetch next k-slab
            int kbase = (it + 1) * 16;
            #pragma unroll
            for (int q = 0; q < 8; q++) {
                int k = kbase + hkoff + q;
                hReg[q] = (k < HP) ? hp_row[k] : 0.f;
            }
            int kk = kbase + wk;
            #pragma unroll
            for (int g = 0; g < 3; g++)
                #pragma unroll
                for (int q = 0; q < 4; q++) {
                    int jj = wj0 + q;
                    wReg[g][q] = (kk < HH && jj < HH) ? W[(size_t)(g * HH + jj) * HH + kk] : 0.f;
                }
        }
        #pragma unroll
        for (int kk = 0; kk < 16; kk += 8) {
            wmma::fragment<wmma::matrix_a, 16, 16, 8, wmma::precision::tf32, wmma::row_major> af[2];
            #pragma unroll
            for (int mi = 0; mi < 2; mi++)
                wmma::load_matrix_sync(af[mi], &sH[(wm * 32 + mi * 16) * 20 + kk], 20);
            #pragma unroll
            for (int g = 0; g < 3; g++)
                #pragma unroll
                for (int ni = 0; ni < 2; ni++) {
                    wmma::fragment<wmma::matrix_b, 16, 16, 8, wmma::precision::tf32, wmma::row_major> bfr;
                    wmma::load_matrix_sync(bfr, &sB[(g * 16 + kk) * 68 + wn * 32 + ni * 16], 68);
                    #pragma unroll
                    for (int mi = 0; mi < 2; mi++)
                        wmma::mma_sync(acc[g][mi][ni], af[mi], bfr, acc[g][mi][ni]);
                }
        }
    }

    // epilogue: per (mi,ni) pass: stage 3 gate tiles, apply GRU nonlinearity
    float* cw = &sC[warp * 3 * 256];
    #pragma unroll
    for (int mi = 0; mi < 2; mi++)
        #pragma unroll
        for (int ni = 0; ni < 2; ni++) {
            #pragma unroll
            for (int g = 0; g < 3; g++)
                wmma::store_matrix_sync(cw + g * 256, acc[g][mi][ni], 16, wmma::mem_row_major);
            __syncwarp();
            #pragma unroll
            for (int q = 0; q < 8; q++) {
                int e = lane * 8 + q;
                int row = e >> 4, col = e & 15;
                int j = j0 + wn * 32 + ni * 16 + col;
                if (j < HH) {
                    int b = b0 + wm * 32 + mi * 16 + row;
                    size_t xb = ((size_t)b * TT + t) * (size_t)G3P;
                    float cr = cw[0 * 256 + e], cz = cw[1 * 256 + e], cn = cw[2 * 256 + e];
                    float r = 1.f / (1.f + expf(-(xg[xb + j] + cr + bhh[j])));
                    float z = 1.f / (1.f + expf(-(xg[xb + HH + j] + cz + bhh[HH + j])));
                    float nn = tanhf(xg[xb + 2 * HH + j] + r * (cn + bhh[2 * HH + j]));
                    hout[(size_t)b * HP + j] = (1.f - z) * nn + z * hprev[(size_t)b * HP + j];
                }
            }
            __syncwarp();
        }
}

// =================== 3. word attention scores (tf32 wmma + fused tanh/proj) ===================
// per block: fixed t, 64 batch rows; 4 n-chunks of 128 (N=460 pad 512); K = 464 = 232+232.
// 8 warps 2x4, warp tile 32x32 per chunk.
__global__ __launch_bounds__(256) void word_score_wmma(
    const float* __restrict__ Ww, const float* __restrict__ bw, const float* __restrict__ pw)
{
    __shared__ float sA[64 * 20];    // 5120 B
    __shared__ float sB[16 * 132];   // 8448 B
    __shared__ float sC[8 * 256];    // 8192 B
    __shared__ float srow[64];

    const int t = blockIdx.x;
    const int b0 = blockIdx.y * 64;
    const int tid = threadIdx.x;
    const int warp = tid >> 5, lane = tid & 31;
    const int wm = warp >> 2, wn = warp & 3;   // 2 x 4: 32 rows, 32 cols

    const float* hf = g_hf + (size_t)(t + 1) * BDIM * HP;
    const float* hr = g_hr + (size_t)t * BDIM * HP;

    if (tid < 64) srow[tid] = 0.f;

    // staging maps
    const int am = tid >> 2, akq = (tid & 3) * 4;     // A: 64 rows x 16k, 4/thread
    const float* hf_row = hf + (size_t)(b0 + am) * HP;
    const float* hr_row = hr + (size_t)(b0 + am) * HP;
    const int bk = tid & 15, bc0 = (tid >> 4) * 8;    // B: 16k x 128n, 8/thread
    const int NIT = 464 / 16;  // 29

    float aReg[4], bReg[8];

    for (int nc = 0; nc < 512; nc += 128) {
        wmma::fragment<wmma::accumulator, 16, 16, 8, float> acc[2][2];
        #pragma unroll
        for (int mi = 0; mi < 2; mi++)
            #pragma unroll
            for (int ni = 0; ni < 2; ni++) wmma::fill_fragment(acc[mi][ni], 0.f);

        {   // preload iter 0 (k = 0..15, always valid for A and Ww)
            #pragma unroll
            for (int q = 0; q < 4; q++) aReg[q] = hf_row[akq + q];
            #pragma unroll
            for (int q = 0; q < 8; q++) {
                int j = nc + bc0 + q;
                bReg[q] = (j < H2) ? Ww[(size_t)bk * H2 + j] : 0.f;
            }
        }

        for (int it = 0; it < NIT; ++it) {
            __syncthreads();
            #pragma unroll
            for (int q = 0; q < 4; q++) sA[am * 20 + akq + q] = TF32(aReg[q]);
            #pragma unroll
            for (int q = 0; q < 8; q++) sB[bk * 132 + bc0 + q] = TF32(bReg[q]);
            __syncthreads();
            if (it + 1 < NIT) {
                int kbase = (it + 1) * 16;
                #pragma unroll
                for (int q = 0; q < 4; q++) {
                    int k = kbase + akq + q;
                    aReg[q] = (k < HP) ? hf_row[k] : hr_row[k - HP];
                }
                int kk = kbase + bk;
                int ksrc = (kk < HH) ? kk : (kk >= HP && kk < HP + HH) ? (kk - 2) : -1;
                #pragma unroll
                for (int q = 0; q < 8; q++) {
                    int j = nc + bc0 + q;
                    bReg[q] = (ksrc >= 0 && j < H2) ? Ww[(size_t)ksrc * H2 + j] : 0.f;
                }
            }
            #pragma unroll
            for (int kk = 0; kk < 16; kk += 8) {
                wmma::fragment<wmma::matrix_a, 16, 16, 8, wmma::precision::tf32, wmma::row_major> af[2];
                #pragma unroll
                for (int mi = 0; mi < 2; mi++)
                    wmma::load_matrix_sync(af[mi], &sA[(wm * 32 + mi * 16) * 20 + kk], 20);
                #pragma unroll
                for (int ni = 0; ni < 2; ni++) {
                    wmma::fragment<wmma::matrix_b, 16, 16, 8, wmma::precision::tf32, wmma::row_major> bfr;
                    wmma::load_matrix_sync(bfr, &sB[kk * 132 + wn * 32 + ni * 16], 132);
                    #pragma unroll
                    for (int mi = 0; mi < 2; mi++)
                        wmma::mma_sync(acc[mi][ni], af[mi], bfr, acc[mi][ni]);
                }
            }
        }
        // fused epilogue: tanh(c + b) * proj, row-sum
        float* cw = &sC[warp * 256];
        #pragma unroll
        for (int mi = 0; mi < 2; mi++)
            #pragma unroll
            for (int ni = 0; ni < 2; ni++) {
                wmma::store_matrix_sync(cw, acc[mi][ni], 16, wmma::mem_row_major);
                __syncwarp();
                float part = 0.f;
                #pragma unroll
                for (int q = 0; q < 8; q++) {
                    int e = lane * 8 + q;
                    int col = e & 15;
                    int j = nc + wn * 32 + ni * 16 + col;
                    if (j < H2) part += tanhf(cw[e] + bw[j]) * pw[j];
                }
                atomicAdd(&srow[wm * 32 + mi * 16 + (lane >> 1)], part);
                __syncwarp();
            }
    }
    __syncthreads();
    if (tid < 64) g_scores[(size_t)(b0 + tid) * TT + t] = srow[tid];
}

// =================== 4. softmax over t + weighted sum -> word_vec ===================
__global__ void word_attn()
{
    __shared__ float alpha[TT];
    __shared__ float red[2];
    const int b = blockIdx.x;
    const int tid = threadIdx.x;
    if (tid < TT) alpha[tid] = g_scores[(size_t)b * TT + tid];
    __syncthreads();
    if (tid == 0) {
        float m = -1e30f;
        for (int t2 = 0; t2 < TT; t2++) m = fmaxf(m, alpha[t2]);
        red[0] = m;
    }
    __syncthreads();
    if (tid < TT) alpha[tid] = expf(alpha[tid] - red[0]);
    __syncthreads();
    if (tid == 0) {
        float ssum = 0.f;
        for (int t2 = 0; t2 < TT; t2++) ssum += alpha[t2];
        red[1] = 1.f / ssum;
    }
    __syncthreads();
    if (tid < TT) alpha[tid] *= red[1];
    __syncthreads();
    const size_t stride = (size_t)BDIM * HP;
    for (int hcol = tid; hcol < H2; hcol += 256) {
        const float* base = (hcol < HH)
            ? (g_hf + stride + (size_t)b * HP + hcol)            // slab t+1
            : (g_hr + (size_t)b * HP + (hcol - HH));             // slab t
        float acc = 0.f;
        #pragma unroll 4
        for (int t2 = 0; t2 < TT; t2++) acc += alpha[t2] * base[(size_t)t2 * stride];
        g_wordvec[(size_t)b * H2 + hcol] = acc;
    }
}

// =================== 5. zero output ===================
__global__ void zero_out(float* __restrict__ out, int n)
{
    int i = blockIdx.x * 256 + threadIdx.x;
    if (i < n) out[i] = 0.f;
}

// =================== 6. sentence attention + FC + scatter ===================
__global__ void sent_kernel(const float* __restrict__ Wsent, const float* __restrict__ bsent,
                            const float* __restrict__ psent, const float* __restrict__ fcW,
                            const float* __restrict__ fcb, const int* __restrict__ pairs,
                            float* __restrict__ out)
{
    __shared__ float wvs[MS][H2];
    __shared__ float score[MS];
    __shared__ float beta[MS];
    __shared__ float sv[H2];
    const int nb = blockIdx.x;
    const int tid = threadIdx.x;

    for (int i = tid; i < MS * H2; i += 256)
        wvs[i / H2][i % H2] = g_wordvec[(size_t)nb * MS * H2 + i];
    if (tid < MS) score[tid] = 0.f;
    __syncthreads();

    for (int j = tid; j < H2; j += 256) {
        float acc[MS];
        #pragma unroll
        for (int s = 0; s < MS; s++) acc[s] = 0.f;
        for (int k = 0; k < H2; k++) {
            float w = Wsent[(size_t)k * H2 + j];
            #pragma unroll
            for (int s = 0; s < MS; s++) acc[s] += wvs[s][k] * w;
        }
        float bb = bsent[j], pp = psent[j];
        #pragma unroll
        for (int s = 0; s < MS; s++) atomicAdd(&score[s], tanhf(acc[s] + bb) * pp);
    }
    __syncthreads();
    if (tid == 0) {
        float m = -1e30f;
        for (int s = 0; s < MS; s++) m = fmaxf(m, score[s]);
        float sum = 0.f;
        for (int s = 0; s < MS; s++) { beta[s] = expf(score[s] - m); sum += beta[s]; }
        float inv = 1.f / sum;
        for (int s = 0; s < MS; s++) beta[s] *= inv;
    }
    __syncthreads();
    for (int hcol = tid; hcol < H2; hcol += 256) {
        float acc = 0.f;
        #pragma unroll
        for (int s = 0; s < MS; s++) acc += beta[s] * wvs[s][hcol];
        sv[hcol] = acc;
    }
    __syncthreads();
    if (tid < NOUT) {
        int o = tid;
        float acc = fcb[o];
        for (int k = 0; k < H2; k++) acc += sv[k] * fcW[(size_t)o * H2 + k];
        int p0 = pairs[nb * 3 + 0];
        int p1 = pairs[nb * 3 + 1];
        int p2 = pairs[nb * 3 + 2];
        out[(((size_t)p0 * NENT + p1) * NENT + p2) * NOUT + o] = acc;
    }
}

// =================== launcher ===================
extern "C" void kernel_launch(void* const* d_in, const int* in_sizes, int n_in,
                              void* d_out, int out_size)
{
    const float* bag       = (const float*)d_in[0];
    const float* W_ih_f    = (const float*)d_in[1];
    const float* W_hh_f    = (const float*)d_in[2];
    const float* b_ih_f    = (const float*)d_in[3];
    const float* b_hh_f    = (const float*)d_in[4];
    const float* W_ih_r    = (const float*)d_in[5];
    const float* W_hh_r    = (const float*)d_in[6];
    const float* b_ih_r    = (const float*)d_in[7];
    const float* b_hh_r    = (const float*)d_in[8];
    const float* W_word    = (const float*)d_in[9];
    const float* b_word    = (const float*)d_in[10];
    const float* proj_word = (const float*)d_in[11];
    const float* W_sent    = (const float*)d_in[12];
    const float* b_sent    = (const float*)d_in[13];
    const float* proj_sent = (const float*)d_in[14];
    const float* fc_W      = (const float*)d_in[15];
    const float* fc_b      = (const float*)d_in[16];
    const int*   pairs     = (const int*)d_in[17];
    float* out = (float*)d_out;

    // 1. input GEMMs (both directions, bias folded via K-extension)
    dim3 gI(G3P / 128, M_TOT / 128, 2);
    input_gemm_wmma<<<gI, 256>>>(bag, W_ih_f, b_ih_f, W_ih_r, b_ih_r);

    // 2. 64 sequential GRU steps (fwd + rev concurrent per launch)
    dim3 gS(4, BDIM / 128, 2);
    for (int s = 0; s < TT; s++)
        gru_step_wmma<<<gS, 256>>>(W_hh_f, b_hh_f, W_hh_r, b_hh_r, s);

    // 3. word attention scores
    dim3 gW(TT, BDIM / 64);
    word_score_wmma<<<gW, 256>>>(W_word, b_word, proj_word);

    // 4. softmax over t + word_vec
    word_attn<<<BDIM, 256>>>();

    // 5. zero output buffer
    int n_out = NDOCS * NENT * NENT * NOUT;
    zero_out<<<(n_out + 255) / 256, 256>>>(out, n_out);

    // 6. sentence attention + FC + scatter
    sent_kernel<<<NBAG, 256>>>(W_sent, b_sent, proj_sent, fc_W, fc_b, pairs, out);
}

// round 9
// speedup vs baseline: 1.6685x; 1.5068x over previous
#include <cuda_runtime.h>
#include <cuda_fp16.h>
#include <mma.h>
#include <math.h>

using namespace nvcuda;

#define NBAG 512
#define MS 8
#define TT 64
#define BDIM 4096          // NBAG*MS
#define INDIM 360
#define HH 230
#define H2 460
#define G3 690
#define G3P 768            // padded xg row stride (elements)
#define NOUT 53
#define NDOCS 32
#define NENT 8
#define HP 232             // padded H (mult of 8)
#define M_TOT (BDIM * TT)  // 262144

// ------------------- scratch (device globals; zero-initialized at module load) -------------------
// xg: fp16, layout [dir][t][b][768] — per-step slab is contiguous.
__device__ __half g_xg[2ull * M_TOT * G3P];
// slab-indexed fp32 hidden states. fwd: h_t at slab t+1 (slab 0 = zeros, never written).
// rev: h_t at slab t (slab TT = zeros, never written). pad cols 230,231 never written.
__device__ float g_hf[(size_t)(TT + 1) * BDIM * HP];
__device__ float g_hr[(size_t)(TT + 1) * BDIM * HP];
__device__ float g_scores[(size_t)BDIM * TT];             // [b][t]
__device__ float g_wordvec[(size_t)BDIM * H2];            // [b][460]

#define H16(x) __float2half(x)

// =================== 1. input GEMM (fp16 wmma): xg[t][b] = bag @ W_ih^T + b_ih ===================
// M' = t*BDIM + b (262144), N=690 (11 tiles of 64), K=360 (23 slabs of 16).
// BM=128, BN=64, 8 warps 4x2, warp 32x32, m16n16k16 half.
__global__ __launch_bounds__(256) void input_gemm_h(
    const float* __restrict__ A,
    const float* __restrict__ Wf, const float* __restrict__ bf_,
    const float* __restrict__ Wr, const float* __restrict__ br_)
{
    __shared__ __half sA[128 * 24];   // [m][k], ld 24
    __shared__ __half sB[16 * 72];    // [k][n], ld 72
    __shared__ float  sC[128 * 64];   // epilogue staging

    const int dir = blockIdx.z;
    const float* W    = dir ? Wr : Wf;
    const float* bias = dir ? br_ : bf_;
    __half* C = g_xg + (size_t)dir * M_TOT * G3P;

    const int n0 = blockIdx.x * 64;
    const int mt0 = blockIdx.y * 128;
    const int tid = threadIdx.x;
    const int warp = tid >> 5;
    const int wm = warp >> 1, wn = warp & 1;

    wmma::fragment<wmma::accumulator, 16, 16, 16, float> acc[2][2];
    #pragma unroll
    for (int i = 0; i < 2; i++)
        #pragma unroll
        for (int j = 0; j < 2; j++) wmma::fill_fragment(acc[i][j], 0.f);

    // staging maps: A row m' -> (t, b) -> bag row b*TT+t
    const int am = tid >> 1, akoff = (tid & 1) * 8;
    const int mprime = mt0 + am;
    const int tt = mprime >> 12, bb = mprime & (BDIM - 1);
    const float* ap = A + ((size_t)bb * TT + tt) * INDIM;
    const int bk = tid & 15, bc0 = (tid >> 4) * 4;

    float aReg[8], bReg[4];
    const int NIT = 23;  // 368 padded k

    {   // preload slab 0 (k 0..15 valid)
        #pragma unroll
        for (int q = 0; q < 8; q++) aReg[q] = ap[akoff + q];
        #pragma unroll
        for (int q = 0; q < 4; q++) {
            int n = n0 + bc0 + q;
            bReg[q] = (n < G3) ? W[(size_t)n * INDIM + bk] : 0.f;
        }
    }

    for (int it = 0; it < NIT; ++it) {
        __syncthreads();
        #pragma unroll
        for (int q = 0; q < 8; q++) sA[am * 24 + akoff + q] = H16(aReg[q]);
        #pragma unroll
        for (int q = 0; q < 4; q++) sB[bk * 72 + bc0 + q] = H16(bReg[q]);
        __syncthreads();
        if (it + 1 < NIT) {   // prefetch next slab
            int kbase = (it + 1) * 16;
            #pragma unroll
            for (int q = 0; q < 8; q++) {
                int k = kbase + akoff + q;
                aReg[q] = (k < INDIM) ? ap[k] : 0.f;
            }
            int kk = kbase + bk;
            #pragma unroll
            for (int q = 0; q < 4; q++) {
                int n = n0 + bc0 + q;
                bReg[q] = (kk < INDIM && n < G3) ? W[(size_t)n * INDIM + kk] : 0.f;
            }
        }
        wmma::fragment<wmma::matrix_a, 16, 16, 16, __half, wmma::row_major> af[2];
        #pragma unroll
        for (int mi = 0; mi < 2; mi++)
            wmma::load_matrix_sync(af[mi], &sA[(wm * 32 + mi * 16) * 24], 24);
        #pragma unroll
        for (int ni = 0; ni < 2; ni++) {
            wmma::fragment<wmma::matrix_b, 16, 16, 16, __half, wmma::row_major> bfr;
            wmma::load_matrix_sync(bfr, &sB[wn * 32 + ni * 16], 72);
            #pragma unroll
            for (int mi = 0; mi < 2; mi++)
                wmma::mma_sync(acc[mi][ni], af[mi], bfr, acc[mi][ni]);
        }
    }
    __syncthreads();
    #pragma unroll
    for (int mi = 0; mi < 2; mi++)
        #pragma unroll
        for (int ni = 0; ni < 2; ni++)
            wmma::store_matrix_sync(&sC[(wm * 32 + mi * 16) * 64 + wn * 32 + ni * 16],
                                    acc[mi][ni], 64, wmma::mem_row_major);
    __syncthreads();
    {   // convert + write half
        int col = tid & 63;
        int r0 = tid >> 6;
        int n = n0 + col;
        if (n < G3) {
            float bv = bias[n];
            #pragma unroll 8
            for (int i = 0; i < 32; i++) {
                int m = r0 * 32 + i;
                C[(size_t)(mt0 + m) * G3P + n] = H16(sC[m * 64 + col] + bv);
            }
        }
    }
}

// =================== 2. GRU step (fp16 wmma, 3 gates fused) ===================
// per block: 64 batch rows x 64 j's. 8 warps 4x2, warp 16x32 per gate. K: 15 slabs of 16.
__global__ __launch_bounds__(256) void gru_step_h(
    const float* __restrict__ Whhf, const float* __restrict__ bhhf,
    const float* __restrict__ Whhr, const float* __restrict__ bhhr,
    int s)
{
    __shared__ __half sH[64 * 24];        // [m][k], ld 24
    __shared__ __half sB3[3 * 16 * 72];   // [g][k][j], ld 72
    __shared__ float  sC[8 * 3 * 256];    // per-warp 3-gate 16x16 staging

    const int dir = blockIdx.z;
    const int t = dir ? (TT - 1 - s) : s;
    const float* W   = dir ? Whhr : Whhf;
    const float* bhh = dir ? bhhr : bhhf;
    const __half* xgt = g_xg + (size_t)dir * M_TOT * G3P + (size_t)t * BDIM * G3P;
    float* hbase = dir ? g_hr : g_hf;
    const int slab_prev = dir ? (t + 1) : t;
    const int slab_out  = dir ? t : (t + 1);
    const float* hprev = hbase + (size_t)slab_prev * BDIM * HP;
    float* hout = hbase + (size_t)slab_out * BDIM * HP;

    const int j0 = blockIdx.x * 64;
    const int b0 = blockIdx.y * 64;
    const int tid = threadIdx.x;
    const int warp = tid >> 5, lane = tid & 31;
    const int wm = warp >> 1, wn = warp & 1;

    wmma::fragment<wmma::accumulator, 16, 16, 16, float> acc[3][2];
    #pragma unroll
    for (int g = 0; g < 3; g++)
        #pragma unroll
        for (int p = 0; p < 2; p++) wmma::fill_fragment(acc[g][p], 0.f);

    // staging maps
    const int hm = tid >> 2, hkq = (tid & 3) * 4;
    const float* hp_row = hprev + (size_t)(b0 + hm) * HP;
    const int wk = tid & 15, wng = tid >> 4;
    const int wj0 = j0 + wng * 4;

    float hReg[4], wReg[3][4];
    const int NIT = 15;  // 240 padded k

    {   // preload slab 0
        #pragma unroll
        for (int q = 0; q < 4; q++) hReg[q] = hp_row[hkq + q];
        #pragma unroll
        for (int g = 0; g < 3; g++)
            #pragma unroll
            for (int q = 0; q < 4; q++) {
                int jj = wj0 + q;
                wReg[g][q] = (jj < HH) ? W[(size_t)(g * HH + jj) * HH + wk] : 0.f;
            }
    }

    for (int it = 0; it < NIT; ++it) {
        __syncthreads();
        #pragma unroll
        for (int q = 0; q < 4; q++) sH[hm * 24 + hkq + q] = H16(hReg[q]);
        #pragma unroll
        for (int g = 0; g < 3; g++)
            #pragma unroll
            for (int q = 0; q < 4; q++)
                sB3[(g * 16 + wk) * 72 + wng * 4 + q] = H16(wReg[g][q]);
        __syncthreads();
        if (it + 1 < NIT) {   // prefetch next slab
            int kbase = (it + 1) * 16;
            #pragma unroll
            for (int q = 0; q < 4; q++) {
                int k = kbase + hkq + q;
                hReg[q] = (k < HP) ? hp_row[k] : 0.f;
            }
            int kk = kbase + wk;
            #pragma unroll
            for (int g = 0; g < 3; g++)
                #pragma unroll
                for (int q = 0; q < 4; q++) {
                    int jj = wj0 + q;
                    wReg[g][q] = (kk < HH && jj < HH) ? W[(size_t)(g * HH + jj) * HH + kk] : 0.f;
                }
        }
        wmma::fragment<wmma::matrix_a, 16, 16, 16, __half, wmma::row_major> af;
        wmma::load_matrix_sync(af, &sH[(wm * 16) * 24], 24);
        #pragma unroll
        for (int g = 0; g < 3; g++)
            #pragma unroll
            for (int p = 0; p < 2; p++) {
                wmma::fragment<wmma::matrix_b, 16, 16, 16, __half, wmma::row_major> bfr;
                wmma::load_matrix_sync(bfr, &sB3[(g * 16) * 72 + wn * 32 + p * 16], 72);
                wmma::mma_sync(acc[g][p], af, bfr, acc[g][p]);
            }
    }

    // epilogue: warp-local GRU nonlinearity; xg is [b][768] half, contiguous per row
    float* cw = &sC[warp * 3 * 256];
    #pragma unroll
    for (int p = 0; p < 2; p++) {
        #pragma unroll
        for (int g = 0; g < 3; g++)
            wmma::store_matrix_sync(cw + g * 256, acc[g][p], 16, wmma::mem_row_major);
        __syncwarp();
        {
            int row = lane >> 1, c0 = (lane & 1) * 8;
            int b = b0 + wm * 16 + row;
            const __half* xr = xgt + (size_t)b * G3P;
            const float* hpr = hprev + (size_t)b * HP;
            float* hor = hout + (size_t)b * HP;
            #pragma unroll
            for (int q = 0; q < 8; q++) {
                int e = row * 16 + c0 + q;
                int j = j0 + wn * 32 + p * 16 + c0 + q;
                if (j < HH) {
                    float cr = cw[0 * 256 + e], cz = cw[1 * 256 + e], cn = cw[2 * 256 + e];
                    float r = 1.f / (1.f + expf(-(__half2float(xr[j]) + cr + bhh[j])));
                    float z = 1.f / (1.f + expf(-(__half2float(xr[HH + j]) + cz + bhh[HH + j])));
                    float nn = tanhf(__half2float(xr[2 * HH + j]) + r * (cn + bhh[2 * HH + j]));
                    hor[j] = (1.f - z) * nn + z * hpr[j];
                }
            }
        }
        __syncwarp();
    }
}

// =================== 3. word attention scores (fp16 wmma + fused tanh/proj) ===================
// per block: fixed t, 64 batch rows; 4 n-chunks of 128; K = 464 = 232+232 (29 slabs).
__global__ __launch_bounds__(256) void word_score_h(
    const float* __restrict__ Ww, const float* __restrict__ bw, const float* __restrict__ pw)
{
    __shared__ __half sA[64 * 24];
    __shared__ __half sB[16 * 136];
    __shared__ float  sC[8 * 256];
    __shared__ float  srow[64];

    const int t = blockIdx.x;
    const int b0 = blockIdx.y * 64;
    const int tid = threadIdx.x;
    const int warp = tid >> 5, lane = tid & 31;
    const int wm = warp >> 2, wn = warp & 3;   // 2 x 4

    const float* hf = g_hf + (size_t)(t + 1) * BDIM * HP;
    const float* hr = g_hr + (size_t)t * BDIM * HP;

    if (tid < 64) srow[tid] = 0.f;

    const int am = tid >> 2, akq = (tid & 3) * 4;
    const float* hf_row = hf + (size_t)(b0 + am) * HP;
    const float* hr_row = hr + (size_t)(b0 + am) * HP;
    const int bk = tid & 15, bc0 = (tid >> 4) * 8;
    const int NIT = 29;

    float aReg[4], bReg[8];

    for (int nc = 0; nc < 512; nc += 128) {
        wmma::fragment<wmma::accumulator, 16, 16, 16, float> acc[2][2];
        #pragma unroll
        for (int mi = 0; mi < 2; mi++)
            #pragma unroll
            for (int ni = 0; ni < 2; ni++) wmma::fill_fragment(acc[mi][ni], 0.f);

        {   // preload slab 0 (k 0..15 valid everywhere)
            #pragma unroll
            for (int q = 0; q < 4; q++) aReg[q] = hf_row[akq + q];
            #pragma unroll
            for (int q = 0; q < 8; q++) {
                int j = nc + bc0 + q;
                bReg[q] = (j < H2) ? Ww[(size_t)bk * H2 + j] : 0.f;
            }
        }

        for (int it = 0; it < NIT; ++it) {
            __syncthreads();
            #pragma unroll
            for (int q = 0; q < 4; q++) sA[am * 24 + akq + q] = H16(aReg[q]);
            #pragma unroll
            for (int q = 0; q < 8; q++) sB[bk * 136 + bc0 + q] = H16(bReg[q]);
            __syncthreads();
            if (it + 1 < NIT) {
                int kbase = (it + 1) * 16;
                #pragma unroll
                for (int q = 0; q < 4; q++) {
                    int k = kbase + akq + q;
                    aReg[q] = (k < HP) ? hf_row[k] : hr_row[k - HP];
                }
                int kk = kbase + bk;
                int ksrc = (kk < HH) ? kk : (kk >= HP && kk < HP + HH) ? (kk - 2) : -1;
                #pragma unroll
                for (int q = 0; q < 8; q++) {
                    int j = nc + bc0 + q;
                    bReg[q] = (ksrc >= 0 && j < H2) ? Ww[(size_t)ksrc * H2 + j] : 0.f;
                }
            }
            wmma::fragment<wmma::matrix_a, 16, 16, 16, __half, wmma::row_major> af[2];
            #pragma unroll
            for (int mi = 0; mi < 2; mi++)
                wmma::load_matrix_sync(af[mi], &sA[(wm * 32 + mi * 16) * 24], 24);
            #pragma unroll
            for (int ni = 0; ni < 2; ni++) {
                wmma::fragment<wmma::matrix_b, 16, 16, 16, __half, wmma::row_major> bfr;
                wmma::load_matrix_sync(bfr, &sB[wn * 32 + ni * 16], 136);
                #pragma unroll
                for (int mi = 0; mi < 2; mi++)
                    wmma::mma_sync(acc[mi][ni], af[mi], bfr, acc[mi][ni]);
            }
        }
        // fused epilogue: tanh(c + b) * proj, row-sum
        float* cw = &sC[warp * 256];
        #pragma unroll
        for (int mi = 0; mi < 2; mi++)
            #pragma unroll
            for (int ni = 0; ni < 2; ni++) {
                wmma::store_matrix_sync(cw, acc[mi][ni], 16, wmma::mem_row_major);
                __syncwarp();
                float part = 0.f;
                #pragma unroll
                for (int q = 0; q < 8; q++) {
                    int e = lane * 8 + q;
                    int col = e & 15;
                    int j = nc + wn * 32 + ni * 16 + col;
                    if (j < H2) part += tanhf(cw[e] + bw[j]) * pw[j];
                }
                atomicAdd(&srow[wm * 32 + mi * 16 + (lane >> 1)], part);
                __syncwarp();
            }
    }
    __syncthreads();
    if (tid < 64) g_scores[(size_t)(b0 + tid) * TT + t] = srow[tid];
}

// =================== 4. softmax over t + weighted sum -> word_vec ===================
__global__ void word_attn()
{
    __shared__ float alpha[TT];
    __shared__ float red[2];
    const int b = blockIdx.x;
    const int tid = threadIdx.x;
    if (tid < TT) alpha[tid] = g_scores[(size_t)b * TT + tid];
    __syncthreads();
    if (tid == 0) {
        float m = -1e30f;
        for (int t2 = 0; t2 < TT; t2++) m = fmaxf(m, alpha[t2]);
        red[0] = m;
    }
    __syncthreads();
    if (tid < TT) alpha[tid] = expf(alpha[tid] - red[0]);
    __syncthreads();
    if (tid == 0) {
        float ssum = 0.f;
        for (int t2 = 0; t2 < TT; t2++) ssum += alpha[t2];
        red[1] = 1.f / ssum;
    }
    __syncthreads();
    if (tid < TT) alpha[tid] *= red[1];
    __syncthreads();
    const size_t stride = (size_t)BDIM * HP;
    for (int hcol = tid; hcol < H2; hcol += 256) {
        const float* base = (hcol < HH)
            ? (g_hf + stride + (size_t)b * HP + hcol)            // slab t+1
            : (g_hr + (size_t)b * HP + (hcol - HH));             // slab t
        float acc = 0.f;
        #pragma unroll 4
        for (int t2 = 0; t2 < TT; t2++) acc += alpha[t2] * base[(size_t)t2 * stride];
        g_wordvec[(size_t)b * H2 + hcol] = acc;
    }
}

// =================== 5. zero output ===================
__global__ void zero_out(float* __restrict__ out, int n)
{
    int i = blockIdx.x * 256 + threadIdx.x;
    if (i < n) out[i] = 0.f;
}

// =================== 6. sentence attention + FC + scatter ===================
__global__ void sent_kernel(const float* __restrict__ Wsent, const float* __restrict__ bsent,
                            const float* __restrict__ psent, const float* __restrict__ fcW,
                            const float* __restrict__ fcb, const int* __restrict__ pairs,
                            float* __restrict__ out)
{
    __shared__ float wvs[MS][H2];
    __shared__ float score[MS];
    __shared__ float beta[MS];
    __shared__ float sv[H2];
    const int nb = blockIdx.x;
    const int tid = threadIdx.x;

    for (int i = tid; i < MS * H2; i += 256)
        wvs[i / H2][i % H2] = g_wordvec[(size_t)nb * MS * H2 + i];
    if (tid < MS) score[tid] = 0.f;
    __syncthreads();

    for (int j = tid; j < H2; j += 256) {
        float acc[MS];
        #pragma unroll
        for (int s = 0; s < MS; s++) acc[s] = 0.f;
        for (int k = 0; k < H2; k++) {
            float w = Wsent[(size_t)k * H2 + j];
            #pragma unroll
            for (int s = 0; s < MS; s++) acc[s] += wvs[s][k] * w;
        }
        float bb = bsent[j], pp = psent[j];
        #pragma unroll
        for (int s = 0; s < MS; s++) atomicAdd(&score[s], tanhf(acc[s] + bb) * pp);
    }
    __syncthreads();
    if (tid == 0) {
        float m = -1e30f;
        for (int s = 0; s < MS; s++) m = fmaxf(m, score[s]);
        float sum = 0.f;
        for (int s = 0; s < MS; s++) { beta[s] = expf(score[s] - m); sum += beta[s]; }
        float inv = 1.f / sum;
        for (int s = 0; s < MS; s++) beta[s] *= inv;
    }
    __syncthreads();
    for (int hcol = tid; hcol < H2; hcol += 256) {
        float acc = 0.f;
        #pragma unroll
        for (int s = 0; s < MS; s++) acc += beta[s] * wvs[s][hcol];
        sv[hcol] = acc;
    }
    __syncthreads();
    if (tid < NOUT) {
        int o = tid;
        float acc = fcb[o];
        for (int k = 0; k < H2; k++) acc += sv[k] * fcW[(size_t)o * H2 + k];
        int p0 = pairs[nb * 3 + 0];
        int p1 = pairs[nb * 3 + 1];
        int p2 = pairs[nb * 3 + 2];
        out[(((size_t)p0 * NENT + p1) * NENT + p2) * NOUT + o] = acc;
    }
}

// =================== launcher ===================
extern "C" void kernel_launch(void* const* d_in, const int* in_sizes, int n_in,
                              void* d_out, int out_size)
{
    const float* bag       = (const float*)d_in[0];
    const float* W_ih_f    = (const float*)d_in[1];
    const float* W_hh_f    = (const float*)d_in[2];
    const float* b_ih_f    = (const float*)d_in[3];
    const float* b_hh_f    = (const float*)d_in[4];
    const float* W_ih_r    = (const float*)d_in[5];
    const float* W_hh_r    = (const float*)d_in[6];
    const float* b_ih_r    = (const float*)d_in[7];
    const float* b_hh_r    = (const float*)d_in[8];
    const float* W_word    = (const float*)d_in[9];
    const float* b_word    = (const float*)d_in[10];
    const float* proj_word = (const float*)d_in[11];
    const float* W_sent    = (const float*)d_in[12];
    const float* b_sent    = (const float*)d_in[13];
    const float* proj_sent = (const float*)d_in[14];
    const float* fc_W      = (const float*)d_in[15];
    const float* fc_b      = (const float*)d_in[16];
    const int*   pairs     = (const int*)d_in[17];
    float* out = (float*)d_out;

    // 1. input GEMMs (both directions), fp16 tensor cores, xg -> [t][b] fp16
    dim3 gI((G3 + 63) / 64, M_TOT / 128, 2);
    input_gemm_h<<<gI, 256>>>(bag, W_ih_f, b_ih_f, W_ih_r, b_ih_r);

    // 2. 64 sequential GRU steps (fwd + rev concurrent per launch), fp16 tensor cores
    dim3 gS((HH + 63) / 64, BDIM / 64, 2);
    for (int s = 0; s < TT; s++)
        gru_step_h<<<gS, 256>>>(W_hh_f, b_hh_f, W_hh_r, b_hh_r, s);

    // 3. word attention scores, fp16 tensor cores + fused tanh/proj epilogue
    dim3 gW(TT, BDIM / 64);
    word_score_h<<<gW, 256>>>(W_word, b_word, proj_word);

    // 4. softmax over t + word_vec
    word_attn<<<BDIM, 256>>>();

    // 5. zero output buffer
    int n_out = NDOCS * NENT * NENT * NOUT;
    zero_out<<<(n_out + 255) / 256, 256>>>(out, n_out);

    // 6. sentence attention + FC + scatter
    sent_kernel<<<NBAG, 256>>>(W_sent, b_sent, proj_sent, fc_W, fc_b, pairs, out);
}

// round 10
// speedup vs baseline: 2.6957x; 1.6157x over previous
#include <cuda_runtime.h>
#include <cuda_fp16.h>
#include <mma.h>
#include <math.h>

using namespace nvcuda;

#define NBAG 512
#define MS 8
#define TT 64
#define BDIM 4096          // NBAG*MS
#define INDIM 360
#define HH 230
#define H2 460
#define G3 690
#define G3P 768            // xg row stride
#define NOUT 53
#define NDOCS 32
#define NENT 8
#define HP 232             // fp32 h row stride
#define HPH 256            // fp16 h row stride / Whh k,j pad
#define KXP 384            // input K pad (360 data + ones@360 + 0s)
#define NXP 704            // Wih n pad
#define WKP 512            // word K pad (256 + 256)
#define WNP 464            // word n pad
#define M_TOT (BDIM * TT)  // 262144

// ------------------- scratch (device globals; zero-initialized at module load) -------------------
__device__ __align__(256) __half g_xh[(size_t)M_TOT * KXP];          // bag fp16, m' = t*BDIM+b
__device__ __align__(256) __half g_Wih[2ull * KXP * NXP];            // [dir][k][n], bias at k=360
__device__ __align__(256) __half g_xg[2ull * M_TOT * G3P];           // [dir][t][b][768]
__device__ __align__(256) __half g_Whh[2ull * 3 * HPH * HPH];        // [dir][g][k][j]
__device__ __align__(256) __half g_Ww[(size_t)WKP * WNP];            // word W, k-gap baked
__device__ float g_hf[(size_t)(TT + 1) * BDIM * HP];                 // fp32 h (blend)
__device__ float g_hr[(size_t)(TT + 1) * BDIM * HP];
__device__ __align__(256) __half g_hfh[(size_t)(TT + 1) * BDIM * HPH];  // fp16 h (MMA/attn)
__device__ __align__(256) __half g_hrh[(size_t)(TT + 1) * BDIM * HPH];
__device__ float g_scores[(size_t)BDIM * TT];
__device__ float g_wordvec[(size_t)BDIM * H2];

#define H16(x) __float2half(x)

// =================== prep kernels ===================
__global__ void conv_x(const float* __restrict__ bag)
{
    size_t idx = (size_t)blockIdx.x * 256 + threadIdx.x;
    const size_t total = (size_t)M_TOT * 46;
    if (idx >= total) return;
    size_t m = idx / 46;
    int kc = (int)(idx % 46) * 8;
    int t = (int)(m >> 12), b = (int)(m & (BDIM - 1));
    __half out[8];
    if (kc < INDIM) {
        const float* src = bag + ((size_t)b * TT + t) * INDIM + kc;
        float4 v0 = *(const float4*)src;
        float4 v1 = *(const float4*)(src + 4);
        out[0] = H16(v0.x); out[1] = H16(v0.y); out[2] = H16(v0.z); out[3] = H16(v0.w);
        out[4] = H16(v1.x); out[5] = H16(v1.y); out[6] = H16(v1.z); out[7] = H16(v1.w);
    } else {   // kc == 360: ones column for bias folding, then zeros
        out[0] = H16(1.f);
        #pragma unroll
        for (int q = 1; q < 8; q++) out[q] = H16(0.f);
    }
    *(uint4*)&g_xh[m * KXP + kc] = *(uint4*)out;
}

__global__ void conv_wih(const float* __restrict__ Wf, const float* __restrict__ bf_,
                         const float* __restrict__ Wr, const float* __restrict__ br_)
{
    int idx = blockIdx.x * 256 + threadIdx.x;
    const int per = 361 * G3;
    if (idx >= 2 * per) return;
    int dir = idx / per, r = idx % per;
    int k = r / G3, n = r % G3;
    const float* W = dir ? Wr : Wf;
    const float* bias = dir ? br_ : bf_;
    float v = (k < INDIM) ? W[(size_t)n * INDIM + k] : bias[n];
    g_Wih[((size_t)dir * KXP + k) * NXP + n] = H16(v);
}

__global__ void conv_whh(const float* __restrict__ Wf, const float* __restrict__ Wr)
{
    int idx = blockIdx.x * 256 + threadIdx.x;
    const int per = 3 * HH * HH;
    if (idx >= 2 * per) return;
    int dir = idx / per, r = idx % per;
    int g = r / (HH * HH); r %= HH * HH;
    int k = r / HH, j = r % HH;
    const float* W = dir ? Wr : Wf;
    g_Whh[(((size_t)dir * 3 + g) * HPH + k) * HPH + j] = H16(W[(size_t)(g * HH + j) * HH + k]);
}

__global__ void conv_ww(const float* __restrict__ Ww)
{
    int idx = blockIdx.x * 256 + threadIdx.x;
    if (idx >= WKP * H2) return;
    int kp = idx / H2, j = idx % H2;
    int ksrc = (kp < HH) ? kp : ((kp >= HPH && kp < HPH + HH) ? (kp - (HPH - HH)) : -1);
    if (ksrc >= 0)
        g_Ww[(size_t)kp * WNP + j] = H16(Ww[(size_t)ksrc * H2 + j]);
}

// =================== 1. input GEMM: xg = xh @ Wih (bias via ones-column) ===================
// M=262144, N=704 (11 tiles of 64), K=384 (12 slabs of 32). 8 warps 4x2, warp 32x32.
__global__ __launch_bounds__(256) void input_gemm2()
{
    __shared__ __half sA[128 * 40];
    __shared__ __half sB[32 * 72];
    __shared__ float  sC[128 * 64];

    const int dir = blockIdx.z;
    const __half* Wh = g_Wih + (size_t)dir * KXP * NXP;
    __half* C = g_xg + (size_t)dir * M_TOT * G3P;

    const int n0 = blockIdx.x * 64;
    const int mt0 = blockIdx.y * 128;
    const int tid = threadIdx.x;
    const int warp = tid >> 5;
    const int wm = warp >> 1, wn = warp & 1;

    wmma::fragment<wmma::accumulator, 16, 16, 16, float> acc[2][2];
    #pragma unroll
    for (int i = 0; i < 2; i++)
        #pragma unroll
        for (int j = 0; j < 2; j++) wmma::fill_fragment(acc[i][j], 0.f);

    const int am = tid >> 1, ak = (tid & 1) * 16;
    const __half* ap = g_xh + (size_t)(mt0 + am) * KXP + ak;
    const int bkr = tid >> 3, bch = (tid & 7) * 8;
    const __half* bp = Wh + (size_t)bkr * NXP + n0 + bch;

    uint4 aR0, aR1, bR;
    aR0 = *(const uint4*)ap;
    aR1 = *(const uint4*)(ap + 8);
    bR  = *(const uint4*)bp;

    const int NIT = KXP / 32;  // 12
    for (int it = 0; it < NIT; ++it) {
        __syncthreads();
        *(uint4*)&sA[am * 40 + ak]     = aR0;
        *(uint4*)&sA[am * 40 + ak + 8] = aR1;
        *(uint4*)&sB[bkr * 72 + bch]   = bR;
        __syncthreads();
        if (it + 1 < NIT) {
            int k0 = (it + 1) * 32;
            aR0 = *(const uint4*)(ap + k0);
            aR1 = *(const uint4*)(ap + k0 + 8);
            bR  = *(const uint4*)(bp + (size_t)k0 * NXP);
        }
        #pragma unroll
        for (int ks = 0; ks < 32; ks += 16) {
            wmma::fragment<wmma::matrix_a, 16, 16, 16, __half, wmma::row_major> af[2];
            #pragma unroll
            for (int mi = 0; mi < 2; mi++)
                wmma::load_matrix_sync(af[mi], &sA[(wm * 32 + mi * 16) * 40 + ks], 40);
            #pragma unroll
            for (int ni = 0; ni < 2; ni++) {
                wmma::fragment<wmma::matrix_b, 16, 16, 16, __half, wmma::row_major> bfr;
                wmma::load_matrix_sync(bfr, &sB[ks * 72 + wn * 32 + ni * 16], 72);
                #pragma unroll
                for (int mi = 0; mi < 2; mi++)
                    wmma::mma_sync(acc[mi][ni], af[mi], bfr, acc[mi][ni]);
            }
        }
    }
    __syncthreads();
    #pragma unroll
    for (int mi = 0; mi < 2; mi++)
        #pragma unroll
        for (int ni = 0; ni < 2; ni++)
            wmma::store_matrix_sync(&sC[(wm * 32 + mi * 16) * 64 + wn * 32 + ni * 16],
                                    acc[mi][ni], 64, wmma::mem_row_major);
    __syncthreads();
    {   // vectorized convert + write (pad cols of g_xg are never read -> unguarded)
        #pragma unroll
        for (int c = 0; c < 4; c++) {
            int lin = c * 256 + tid;
            int row = lin >> 3, ch = (lin & 7) * 8;
            const float* s = &sC[row * 64 + ch];
            __half out[8];
            #pragma unroll
            for (int q = 0; q < 8; q++) out[q] = H16(s[q]);
            *(uint4*)&C[(size_t)(mt0 + row) * G3P + n0 + ch] = *(uint4*)out;
        }
    }
}

// =================== 2. GRU step (fp16, pre-converted operands, BK=32) ===================
// per block: 64 b x 64 j, 3 gates. K: 8 slabs of 32 (pad zeros). 8 warps 4x2.
__global__ __launch_bounds__(256, 2) void gru_step2(
    const float* __restrict__ bhhf, const float* __restrict__ bhhr, int s)
{
    __shared__ __half sH[64 * 40];
    __shared__ __half sW[3 * 32 * 72];
    __shared__ float  sC[8 * 3 * 256];

    const int dir = blockIdx.z;
    const int t = dir ? (TT - 1 - s) : s;
    const float* bhh = dir ? bhhr : bhhf;
    const __half* xgt = g_xg + (size_t)dir * M_TOT * G3P + (size_t)t * BDIM * G3P;
    const __half* Whd = g_Whh + (size_t)dir * 3 * HPH * HPH;
    float* hbase = dir ? g_hr : g_hf;
    __half* hhbase = dir ? g_hrh : g_hfh;
    const int slab_prev = dir ? (t + 1) : t;
    const int slab_out  = dir ? t : (t + 1);
    const float*  hprev  = hbase + (size_t)slab_prev * BDIM * HP;
    float*        hout   = hbase + (size_t)slab_out * BDIM * HP;
    const __half* hprevh = hhbase + (size_t)slab_prev * BDIM * HPH;
    __half*       houth  = hhbase + (size_t)slab_out * BDIM * HPH;

    const int j0 = blockIdx.x * 64;
    const int b0 = blockIdx.y * 64;
    const int tid = threadIdx.x;
    const int warp = tid >> 5, lane = tid & 31;
    const int wm = warp >> 1, wn = warp & 1;

    wmma::fragment<wmma::accumulator, 16, 16, 16, float> acc[3][2];
    #pragma unroll
    for (int g = 0; g < 3; g++)
        #pragma unroll
        for (int p = 0; p < 2; p++) wmma::fill_fragment(acc[g][p], 0.f);

    // staging maps (pure vector copies; all pads are zero)
    const int hrow = tid & 63, hch = (tid >> 6) * 8;
    const __half* hp = hprevh + (size_t)(b0 + hrow) * HPH + hch;
    int sWoff[3];
    const __half* wp[3];
    #pragma unroll
    for (int c = 0; c < 3; c++) {
        int lin = c * 256 + tid;
        int g = lin >> 8, rem = lin & 255;
        int kr = rem >> 3, ch = (rem & 7) * 8;
        sWoff[c] = (g * 32 + kr) * 72 + ch;
        wp[c] = Whd + ((size_t)g * HPH + kr) * HPH + j0 + ch;
    }

    uint4 hR = *(const uint4*)hp;
    uint4 wR[3];
    #pragma unroll
    for (int c = 0; c < 3; c++) wR[c] = *(const uint4*)wp[c];

    const int NIT = HPH / 32;  // 8
    for (int it = 0; it < NIT; ++it) {
        __syncthreads();
        *(uint4*)&sH[hrow * 40 + hch] = hR;
        #pragma unroll
        for (int c = 0; c < 3; c++) *(uint4*)&sW[sWoff[c]] = wR[c];
        __syncthreads();
        if (it + 1 < NIT) {
            int k0 = (it + 1) * 32;
            hR = *(const uint4*)(hp + k0);
            #pragma unroll
            for (int c = 0; c < 3; c++) wR[c] = *(const uint4*)(wp[c] + (size_t)k0 * HPH);
        }
        #pragma unroll
        for (int ks = 0; ks < 32; ks += 16) {
            wmma::fragment<wmma::matrix_a, 16, 16, 16, __half, wmma::row_major> af;
            wmma::load_matrix_sync(af, &sH[(wm * 16) * 40 + ks], 40);
            #pragma unroll
            for (int g = 0; g < 3; g++)
                #pragma unroll
                for (int p = 0; p < 2; p++) {
                    wmma::fragment<wmma::matrix_b, 16, 16, 16, __half, wmma::row_major> bfr;
                    wmma::load_matrix_sync(bfr, &sW[(g * 32 + ks) * 72 + wn * 32 + p * 16], 72);
                    wmma::mma_sync(acc[g][p], af, bfr, acc[g][p]);
                }
        }
    }

    // epilogue: GRU nonlinearity; dual fp32 + fp16 h writes
    float* cw = &sC[warp * 3 * 256];
    #pragma unroll
    for (int p = 0; p < 2; p++) {
        #pragma unroll
        for (int g = 0; g < 3; g++)
            wmma::store_matrix_sync(cw + g * 256, acc[g][p], 16, wmma::mem_row_major);
        __syncwarp();
        {
            int row = lane >> 1, c0 = (lane & 1) * 8;
            int b = b0 + wm * 16 + row;
            const __half* xr = xgt + (size_t)b * G3P;
            const float* hpr = hprev + (size_t)b * HP;
            float* hor = hout + (size_t)b * HP;
            __half* horh = houth + (size_t)b * HPH;
            #pragma unroll
            for (int q = 0; q < 8; q++) {
                int e = row * 16 + c0 + q;
                int j = j0 + wn * 32 + p * 16 + c0 + q;
                if (j < HH) {
                    float cr = cw[0 * 256 + e], cz = cw[1 * 256 + e], cn = cw[2 * 256 + e];
                    float r = 1.f / (1.f + __expf(-(__half2float(xr[j]) + cr + bhh[j])));
                    float z = 1.f / (1.f + __expf(-(__half2float(xr[HH + j]) + cz + bhh[HH + j])));
                    float nn = tanhf(__half2float(xr[2 * HH + j]) + r * (cn + bhh[2 * HH + j]));
                    float val = (1.f - z) * nn + z * hpr[j];
                    hor[j] = val;
                    horh[j] = H16(val);
                }
            }
        }
        __syncwarp();
    }
}

// =================== 3. word attention scores (fp16, pre-converted W, BK=32) ===================
// per block: fixed t, 64 b rows; 4 n-chunks of 128; K = 512 (16 slabs). 8 warps 2x4.
__global__ __launch_bounds__(256, 2) void word_score2(
    const float* __restrict__ bw, const float* __restrict__ pw)
{
    __shared__ __half sA[64 * 40];
    __shared__ __half sB[32 * 136];
    __shared__ float  sC[8 * 256];
    __shared__ float  srow[64];

    const int t = blockIdx.x;
    const int b0 = blockIdx.y * 64;
    const int tid = threadIdx.x;
    const int warp = tid >> 5, lane = tid & 31;
    const int wm = warp >> 2, wn = warp & 3;

    const __half* hfh = g_hfh + (size_t)(t + 1) * BDIM * HPH;
    const __half* hrh = g_hrh + (size_t)t * BDIM * HPH;

    if (tid < 64) srow[tid] = 0.f;

    const int arow = tid & 63, ach = (tid >> 6) * 8;
    const __half* af_p = hfh + (size_t)(b0 + arow) * HPH + ach;
    const __half* ar_p = hrh + (size_t)(b0 + arow) * HPH + ach;
    const int NIT = WKP / 32;  // 16

    for (int nc = 0; nc < 512; nc += 128) {
        wmma::fragment<wmma::accumulator, 16, 16, 16, float> acc[2][2];
        #pragma unroll
        for (int mi = 0; mi < 2; mi++)
            #pragma unroll
            for (int ni = 0; ni < 2; ni++) wmma::fill_fragment(acc[mi][ni], 0.f);

        uint4 aR = *(const uint4*)af_p;  // k0=0 < 256
        uint4 bR[2];
        #pragma unroll
        for (int c = 0; c < 2; c++) {
            int lin = c * 256 + tid;
            int kr = lin >> 4, ch = (lin & 15) * 8;
            bR[c] = *(const uint4*)&g_Ww[(size_t)kr * WNP + nc + ch];
        }

        for (int it = 0; it < NIT; ++it) {
            __syncthreads();
            *(uint4*)&sA[arow * 40 + ach] = aR;
            #pragma unroll
            for (int c = 0; c < 2; c++) {
                int lin = c * 256 + tid;
                int kr = lin >> 4, ch = (lin & 15) * 8;
                *(uint4*)&sB[kr * 136 + ch] = bR[c];
            }
            __syncthreads();
            if (it + 1 < NIT) {
                int k0 = (it + 1) * 32;
                aR = (k0 < HPH) ? *(const uint4*)(af_p + k0)
                                : *(const uint4*)(ar_p + (k0 - HPH));
                #pragma unroll
                for (int c = 0; c < 2; c++) {
                    int lin = c * 256 + tid;
                    int kr = lin >> 4, ch = (lin & 15) * 8;
                    bR[c] = *(const uint4*)&g_Ww[(size_t)(k0 + kr) * WNP + nc + ch];
                }
            }
            #pragma unroll
            for (int ks = 0; ks < 32; ks += 16) {
                wmma::fragment<wmma::matrix_a, 16, 16, 16, __half, wmma::row_major> af[2];
                #pragma unroll
                for (int mi = 0; mi < 2; mi++)
                    wmma::load_matrix_sync(af[mi], &sA[(wm * 32 + mi * 16) * 40 + ks], 40);
                #pragma unroll
                for (int ni = 0; ni < 2; ni++) {
                    wmma::fragment<wmma::matrix_b, 16, 16, 16, __half, wmma::row_major> bfr;
                    wmma::load_matrix_sync(bfr, &sB[ks * 136 + wn * 32 + ni * 16], 136);
                    #pragma unroll
                    for (int mi = 0; mi < 2; mi++)
                        wmma::mma_sync(acc[mi][ni], af[mi], bfr, acc[mi][ni]);
                }
            }
        }
        // fused epilogue: tanh(c + b) * proj, row-sum
        float* cw = &sC[warp * 256];
        #pragma unroll
        for (int mi = 0; mi < 2; mi++)
            #pragma unroll
            for (int ni = 0; ni < 2; ni++) {
                wmma::store_matrix_sync(cw, acc[mi][ni], 16, wmma::mem_row_major);
                __syncwarp();
                float part = 0.f;
                #pragma unroll
                for (int q = 0; q < 8; q++) {
                    int e = lane * 8 + q;
                    int col = e & 15;
                    int j = nc + wn * 32 + ni * 16 + col;
                    if (j < H2) part += tanhf(cw[e] + bw[j]) * pw[j];
                }
                atomicAdd(&srow[wm * 32 + mi * 16 + (lane >> 1)], part);
                __syncwarp();
            }
    }
    __syncthreads();
    if (tid < 64) g_scores[(size_t)(b0 + tid) * TT + t] = srow[tid];
}

// =================== 4. softmax over t + weighted sum (fp16 h reads) ===================
__global__ void word_attn()
{
    __shared__ float alpha[TT];
    __shared__ float red[2];
    const int b = blockIdx.x;
    const int tid = threadIdx.x;
    if (tid < TT) alpha[tid] = g_scores[(size_t)b * TT + tid];
    __syncthreads();
    if (tid == 0) {
        float m = -1e30f;
        for (int t2 = 0; t2 < TT; t2++) m = fmaxf(m, alpha[t2]);
        red[0] = m;
    }
    __syncthreads();
    if (tid < TT) alpha[tid] = __expf(alpha[tid] - red[0]);
    __syncthreads();
    if (tid == 0) {
        float ssum = 0.f;
        for (int t2 = 0; t2 < TT; t2++) ssum += alpha[t2];
        red[1] = 1.f / ssum;
    }
    __syncthreads();
    if (tid < TT) alpha[tid] *= red[1];
    __syncthreads();
    const size_t stride = (size_t)BDIM * HPH;
    for (int hcol = tid; hcol < H2; hcol += 256) {
        const __half* base = (hcol < HH)
            ? (g_hfh + stride + (size_t)b * HPH + hcol)          // slab t+1
            : (g_hrh + (size_t)b * HPH + (hcol - HH));           // slab t
        float acc = 0.f;
        #pragma unroll 4
        for (int t2 = 0; t2 < TT; t2++) acc += alpha[t2] * __half2float(base[(size_t)t2 * stride]);
        g_wordvec[(size_t)b * H2 + hcol] = acc;
    }
}

// =================== 5. zero output ===================
__global__ void zero_out(float* __restrict__ out, int n)
{
    int i = blockIdx.x * 256 + threadIdx.x;
    if (i < n) out[i] = 0.f;
}

// =================== 6. sentence attention + FC + scatter ===================
__global__ void sent_kernel(const float* __restrict__ Wsent, const float* __restrict__ bsent,
                            const float* __restrict__ psent, const float* __restrict__ fcW,
                            const float* __restrict__ fcb, const int* __restrict__ pairs,
                            float* __restrict__ out)
{
    __shared__ float wvs[MS][H2];
    __shared__ float score[MS];
    __shared__ float beta[MS];
    __shared__ float sv[H2];
    const int nb = blockIdx.x;
    const int tid = threadIdx.x;

    for (int i = tid; i < MS * H2; i += 256)
        wvs[i / H2][i % H2] = g_wordvec[(size_t)nb * MS * H2 + i];
    if (tid < MS) score[tid] = 0.f;
    __syncthreads();

    for (int j = tid; j < H2; j += 256) {
        float acc[MS];
        #pragma unroll
        for (int s = 0; s < MS; s++) acc[s] = 0.f;
        for (int k = 0; k < H2; k++) {
            float w = Wsent[(size_t)k * H2 + j];
            #pragma unroll
            for (int s = 0; s < MS; s++) acc[s] += wvs[s][k] * w;
        }
        float bb = bsent[j], pp = psent[j];
        #pragma unroll
        for (int s = 0; s < MS; s++) atomicAdd(&score[s], tanhf(acc[s] + bb) * pp);
    }
    __syncthreads();
    if (tid == 0) {
        float m = -1e30f;
        for (int s = 0; s < MS; s++) m = fmaxf(m, score[s]);
        float sum = 0.f;
        for (int s = 0; s < MS; s++) { beta[s] = __expf(score[s] - m); sum += beta[s]; }
        float inv = 1.f / sum;
        for (int s = 0; s < MS; s++) beta[s] *= inv;
    }
    __syncthreads();
    for (int hcol = tid; hcol < H2; hcol += 256) {
        float acc = 0.f;
        #pragma unroll
        for (int s = 0; s < MS; s++) acc += beta[s] * wvs[s][hcol];
        sv[hcol] = acc;
    }
    __syncthreads();
    if (tid < NOUT) {
        int o = tid;
        float acc = fcb[o];
        for (int k = 0; k < H2; k++) acc += sv[k] * fcW[(size_t)o * H2 + k];
        int p0 = pairs[nb * 3 + 0];
        int p1 = pairs[nb * 3 + 1];
        int p2 = pairs[nb * 3 + 2];
        out[(((size_t)p0 * NENT + p1) * NENT + p2) * NOUT + o] = acc;
    }
}

// =================== launcher ===================
extern "C" void kernel_launch(void* const* d_in, const int* in_sizes, int n_in,
                              void* d_out, int out_size)
{
    const float* bag       = (const float*)d_in[0];
    const float* W_ih_f    = (const float*)d_in[1];
    const float* W_hh_f    = (const float*)d_in[2];
    const float* b_ih_f    = (const float*)d_in[3];
    const float* b_hh_f    = (const float*)d_in[4];
    const float* W_ih_r    = (const float*)d_in[5];
    const float* W_hh_r    = (const float*)d_in[6];
    const float* b_ih_r    = (const float*)d_in[7];
    const float* b_hh_r    = (const float*)d_in[8];
    const float* W_word    = (const float*)d_in[9];
    const float* b_word    = (const float*)d_in[10];
    const float* proj_word = (const float*)d_in[11];
    const float* W_sent    = (const float*)d_in[12];
    const float* b_sent    = (const float*)d_in[13];
    const float* proj_sent = (const float*)d_in[14];
    const float* fc_W      = (const float*)d_in[15];
    const float* fc_b      = (const float*)d_in[16];
    const int*   pairs     = (const int*)d_in[17];
    float* out = (float*)d_out;

    // 0. pre-convert operands to fp16 MMA-ready layouts
    {
        size_t nx = (size_t)M_TOT * 46;
        conv_x<<<(unsigned)((nx + 255) / 256), 256>>>(bag);
        int nwih = 2 * 361 * G3;
        conv_wih<<<(nwih + 255) / 256, 256>>>(W_ih_f, b_ih_f, W_ih_r, b_ih_r);
        int nwhh = 2 * 3 * HH * HH;
        conv_whh<<<(nwhh + 255) / 256, 256>>>(W_hh_f, W_hh_r);
        int nww = WKP * H2;
        conv_ww<<<(nww + 255) / 256, 256>>>(W_word);
    }

    // 1. input GEMMs (bias folded via ones-column)
    dim3 gI(11, M_TOT / 128, 2);
    input_gemm2<<<gI, 256>>>();

    // 2. 64 sequential GRU steps (fwd + rev concurrent per launch)
    dim3 gS(4, BDIM / 64, 2);
    for (int s = 0; s < TT; s++)
        gru_step2<<<gS, 256>>>(b_hh_f, b_hh_r, s);

    // 3. word attention scores
    dim3 gW(TT, BDIM / 64);
    word_score2<<<gW, 256>>>(b_word, proj_word);

    // 4. softmax over t + word_vec
    word_attn<<<BDIM, 256>>>();

    // 5. zero output buffer
    int n_out = NDOCS * NENT * NENT * NOUT;
    zero_out<<<(n_out + 255) / 256, 256>>>(out, n_out);

    // 6. sentence attention + FC + scatter
    sent_kernel<<<NBAG, 256>>>(W_sent, b_sent, proj_sent, fc_W, fc_b, pairs, out);
}

// round 11
// speedup vs baseline: 2.9336x; 1.0882x over previous
#include <cuda_runtime.h>
#include <cuda_fp16.h>
#include <mma.h>
#include <math.h>

using namespace nvcuda;

#define NBAG 512
#define MS 8
#define TT 64
#define BDIM 4096          // NBAG*MS
#define INDIM 360
#define HH 230
#define H2 460
#define G3 690
#define G3P 768            // xg row stride
#define NOUT 53
#define NDOCS 32
#define NENT 8
#define HP 232             // fp32 h row stride
#define HPH 256            // fp16 h row stride / Whh k,j pad
#define KXP 384            // input K pad (360 data + ones@360 + 0s)
#define NXP 768            // Wih n pad (= G3P, unguarded tiles)
#define WKP 512            // word K pad (256 + 256)
#define WNP 464            // word n pad
#define M_TOT (BDIM * TT)  // 262144

// ------------------- scratch (device globals; zero-initialized at module load) -------------------
__device__ __align__(256) __half g_xh[(size_t)M_TOT * KXP];          // bag fp16, m' = t*BDIM+b
__device__ __align__(256) __half g_Wih[2ull * KXP * NXP];            // [dir][k][n], bias at k=360
__device__ __align__(256) __half g_xg[2ull * M_TOT * G3P];           // [dir][t][b][768]
__device__ __align__(256) __half g_Whh[2ull * 3 * HPH * HPH];        // [dir][g][k][j]
__device__ __align__(256) __half g_Ww[(size_t)WKP * WNP];            // word W, k-gap baked
__device__ float g_hf[(size_t)(TT + 1) * BDIM * HP];                 // fp32 h (blend)
__device__ float g_hr[(size_t)(TT + 1) * BDIM * HP];
__device__ __align__(256) __half g_hfh[(size_t)(TT + 1) * BDIM * HPH];  // fp16 h (MMA/attn)
__device__ __align__(256) __half g_hrh[(size_t)(TT + 1) * BDIM * HPH];
__device__ float g_scores[(size_t)BDIM * TT];
__device__ float g_wordvec[(size_t)BDIM * H2];

#define H16(x) __float2half(x)

// =================== prep kernels ===================
__global__ void conv_x(const float* __restrict__ bag)
{
    size_t idx = (size_t)blockIdx.x * 256 + threadIdx.x;
    const size_t total = (size_t)M_TOT * 46;
    if (idx >= total) return;
    size_t m = idx / 46;
    int kc = (int)(idx % 46) * 8;
    int t = (int)(m >> 12), b = (int)(m & (BDIM - 1));
    __half out[8];
    if (kc < INDIM) {
        const float* src = bag + ((size_t)b * TT + t) * INDIM + kc;
        float4 v0 = *(const float4*)src;
        float4 v1 = *(const float4*)(src + 4);
        out[0] = H16(v0.x); out[1] = H16(v0.y); out[2] = H16(v0.z); out[3] = H16(v0.w);
        out[4] = H16(v1.x); out[5] = H16(v1.y); out[6] = H16(v1.z); out[7] = H16(v1.w);
    } else {   // kc == 360: ones column for bias folding, then zeros
        out[0] = H16(1.f);
        #pragma unroll
        for (int q = 1; q < 8; q++) out[q] = H16(0.f);
    }
    *(uint4*)&g_xh[m * KXP + kc] = *(uint4*)out;
}

__global__ void conv_wih(const float* __restrict__ Wf, const float* __restrict__ bf_,
                         const float* __restrict__ Wr, const float* __restrict__ br_)
{
    int idx = blockIdx.x * 256 + threadIdx.x;
    const int per = 361 * G3;
    if (idx >= 2 * per) return;
    int dir = idx / per, r = idx % per;
    int k = r / G3, n = r % G3;
    const float* W = dir ? Wr : Wf;
    const float* bias = dir ? br_ : bf_;
    float v = (k < INDIM) ? W[(size_t)n * INDIM + k] : bias[n];
    g_Wih[((size_t)dir * KXP + k) * NXP + n] = H16(v);
}

__global__ void conv_whh(const float* __restrict__ Wf, const float* __restrict__ Wr)
{
    int idx = blockIdx.x * 256 + threadIdx.x;
    const int per = 3 * HH * HH;
    if (idx >= 2 * per) return;
    int dir = idx / per, r = idx % per;
    int g = r / (HH * HH); r %= HH * HH;
    int k = r / HH, j = r % HH;
    const float* W = dir ? Wr : Wf;
    g_Whh[(((size_t)dir * 3 + g) * HPH + k) * HPH + j] = H16(W[(size_t)(g * HH + j) * HH + k]);
}

__global__ void conv_ww(const float* __restrict__ Ww)
{
    int idx = blockIdx.x * 256 + threadIdx.x;
    if (idx >= WKP * H2) return;
    int kp = idx / H2, j = idx % H2;
    int ksrc = (kp < HH) ? kp : ((kp >= HPH && kp < HPH + HH) ? (kp - (HPH - HH)) : -1);
    if (ksrc >= 0)
        g_Ww[(size_t)kp * WNP + j] = H16(Ww[(size_t)ksrc * H2 + j]);
}

// =================== 1. input GEMM: xg = xh @ Wih (bias via ones-column) ===================
// M=262144, N=768 (6 tiles of 128), K=384 (12 slabs of 32). 8 warps 4x2, warp 32x64.
// 2-stage smem double buffering; unguarded (pads zero / pad cols never read).
__global__ __launch_bounds__(256) void input_gemm3()
{
    __shared__ __half sA[2][128 * 40];   // 2 x 10240 B
    __shared__ __half sB[2][32 * 136];   // 2 x 8704 B
    __shared__ float  sC[8 * 256];       // per-warp epilogue staging, 8 KB

    const int dir = blockIdx.z;
    const __half* Wh = g_Wih + (size_t)dir * KXP * NXP;
    __half* C = g_xg + (size_t)dir * M_TOT * G3P;

    const int n0 = blockIdx.x * 128;
    const int mt0 = blockIdx.y * 128;
    const int tid = threadIdx.x;
    const int warp = tid >> 5, lane = tid & 31;
    const int wm = warp >> 1, wn = warp & 1;

    wmma::fragment<wmma::accumulator, 16, 16, 16, float> acc[2][4];
    #pragma unroll
    for (int i = 0; i < 2; i++)
        #pragma unroll
        for (int j = 0; j < 4; j++) wmma::fill_fragment(acc[i][j], 0.f);

    // staging maps
    const int am = tid >> 1, ak = (tid & 1) * 16;          // 2 uint4 at ak, ak+8
    const __half* ap = g_xh + (size_t)(mt0 + am) * KXP + ak;
    const int bkr = tid >> 3, bch = (tid & 7) * 16;        // 2 uint4 at bch, bch+8
    const __half* bp = Wh + (size_t)bkr * NXP + n0 + bch;

    uint4 aR0 = *(const uint4*)ap;
    uint4 aR1 = *(const uint4*)(ap + 8);
    uint4 bR0 = *(const uint4*)bp;
    uint4 bR1 = *(const uint4*)(bp + 8);

    const int NIT = KXP / 32;  // 12
    // prologue: fill buf 0
    *(uint4*)&sA[0][am * 40 + ak]     = aR0;
    *(uint4*)&sA[0][am * 40 + ak + 8] = aR1;
    *(uint4*)&sB[0][bkr * 136 + bch]     = bR0;
    *(uint4*)&sB[0][bkr * 136 + bch + 8] = bR1;
    __syncthreads();

    for (int it = 0; it < NIT; ++it) {
        const int cur = it & 1;
        if (it + 1 < NIT) {   // issue next slab's loads before MMAs
            int k0 = (it + 1) * 32;
            aR0 = *(const uint4*)(ap + k0);
            aR1 = *(const uint4*)(ap + k0 + 8);
            bR0 = *(const uint4*)(bp + (size_t)k0 * NXP);
            bR1 = *(const uint4*)(bp + (size_t)k0 * NXP + 8);
        }
        #pragma unroll
        for (int ks = 0; ks < 32; ks += 16) {
            wmma::fragment<wmma::matrix_a, 16, 16, 16, __half, wmma::row_major> af[2];
            #pragma unroll
            for (int mi = 0; mi < 2; mi++)
                wmma::load_matrix_sync(af[mi], &sA[cur][(wm * 32 + mi * 16) * 40 + ks], 40);
            #pragma unroll
            for (int ni = 0; ni < 4; ni++) {
                wmma::fragment<wmma::matrix_b, 16, 16, 16, __half, wmma::row_major> bfr;
                wmma::load_matrix_sync(bfr, &sB[cur][ks * 136 + wn * 64 + ni * 16], 136);
                #pragma unroll
                for (int mi = 0; mi < 2; mi++)
                    wmma::mma_sync(acc[mi][ni], af[mi], bfr, acc[mi][ni]);
            }
        }
        if (it + 1 < NIT) {
            const int nxt = cur ^ 1;
            *(uint4*)&sA[nxt][am * 40 + ak]     = aR0;
            *(uint4*)&sA[nxt][am * 40 + ak + 8] = aR1;
            *(uint4*)&sB[nxt][bkr * 136 + bch]     = bR0;
            *(uint4*)&sB[nxt][bkr * 136 + bch + 8] = bR1;
            __syncthreads();
        }
    }

    // per-warp epilogue: frag -> smem -> fp16 global (pads writable)
    float* cw = &sC[warp * 256];
    const int erow = lane >> 1, ec0 = (lane & 1) * 8;
    #pragma unroll
    for (int mi = 0; mi < 2; mi++)
        #pragma unroll
        for (int ni = 0; ni < 4; ni++) {
            wmma::store_matrix_sync(cw, acc[mi][ni], 16, wmma::mem_row_major);
            __syncwarp();
            const float* s = &cw[erow * 16 + ec0];
            __half out[8];
            #pragma unroll
            for (int q = 0; q < 8; q++) out[q] = H16(s[q]);
            *(uint4*)&C[(size_t)(mt0 + wm * 32 + mi * 16 + erow) * G3P
                        + n0 + wn * 64 + ni * 16 + ec0] = *(uint4*)out;
            __syncwarp();
        }
}

// =================== 2. GRU step (fp16, double-buffered, sC aliased) ===================
// per block: 64 b x 64 j, 3 gates. K: 8 slabs of 32. 8 warps 4x2 (warp 16x32 per gate).
__global__ __launch_bounds__(256, 2) void gru_step3(
    const float* __restrict__ bhhf, const float* __restrict__ bhhr, int s)
{
    // mainloop buffers: sH 2x5120B @0, sW 2x13824B @10240; epilogue sC (24576B) aliases @0
    __shared__ __align__(16) char smemRaw[10240 + 27648];
    __half (*sH)[64 * 40] = (__half (*)[64 * 40])smemRaw;
    __half (*sW)[3 * 32 * 72] = (__half (*)[3 * 32 * 72])(smemRaw + 10240);
    float* sCall = (float*)smemRaw;

    const int dir = blockIdx.z;
    const int t = dir ? (TT - 1 - s) : s;
    const float* bhh = dir ? bhhr : bhhf;
    const __half* xgt = g_xg + (size_t)dir * M_TOT * G3P + (size_t)t * BDIM * G3P;
    const __half* Whd = g_Whh + (size_t)dir * 3 * HPH * HPH;
    float* hbase = dir ? g_hr : g_hf;
    __half* hhbase = dir ? g_hrh : g_hfh;
    const int slab_prev = dir ? (t + 1) : t;
    const int slab_out  = dir ? t : (t + 1);
    const float*  hprev  = hbase + (size_t)slab_prev * BDIM * HP;
    float*        hout   = hbase + (size_t)slab_out * BDIM * HP;
    const __half* hprevh = hhbase + (size_t)slab_prev * BDIM * HPH;
    __half*       houth  = hhbase + (size_t)slab_out * BDIM * HPH;

    const int j0 = blockIdx.x * 64;
    const int b0 = blockIdx.y * 64;
    const int tid = threadIdx.x;
    const int warp = tid >> 5, lane = tid & 31;
    const int wm = warp >> 1, wn = warp & 1;

    wmma::fragment<wmma::accumulator, 16, 16, 16, float> acc[3][2];
    #pragma unroll
    for (int g = 0; g < 3; g++)
        #pragma unroll
        for (int p = 0; p < 2; p++) wmma::fill_fragment(acc[g][p], 0.f);

    // staging maps (coalesced: consecutive tid -> consecutive addresses)
    const int hrow = tid >> 2, hch = (tid & 3) * 8;
    const __half* hp = hprevh + (size_t)(b0 + hrow) * HPH + hch;
    const int wkr = tid >> 3, wch = (tid & 7) * 8;         // per gate: 32 k-rows x 64 j
    const __half* wp0 = Whd + (size_t)wkr * HPH + j0 + wch;        // g=0
    const size_t gstep = (size_t)HPH * HPH;

    uint4 hR = *(const uint4*)hp;
    uint4 wR[3];
    #pragma unroll
    for (int g = 0; g < 3; g++) wR[g] = *(const uint4*)(wp0 + g * gstep);

    const int NIT = HPH / 32;  // 8
    // prologue: fill buf 0
    *(uint4*)&sH[0][hrow * 40 + hch] = hR;
    #pragma unroll
    for (int g = 0; g < 3; g++) *(uint4*)&sW[0][(g * 32 + wkr) * 72 + wch] = wR[g];
    __syncthreads();

    for (int it = 0; it < NIT; ++it) {
        const int cur = it & 1;
        if (it + 1 < NIT) {
            int k0 = (it + 1) * 32;
            hR = *(const uint4*)(hp + k0);
            #pragma unroll
            for (int g = 0; g < 3; g++)
                wR[g] = *(const uint4*)(wp0 + g * gstep + (size_t)k0 * HPH);
        }
        #pragma unroll
        for (int ks = 0; ks < 32; ks += 16) {
            wmma::fragment<wmma::matrix_a, 16, 16, 16, __half, wmma::row_major> af;
            wmma::load_matrix_sync(af, &sH[cur][(wm * 16) * 40 + ks], 40);
            #pragma unroll
            for (int g = 0; g < 3; g++)
                #pragma unroll
                for (int p = 0; p < 2; p++) {
                    wmma::fragment<wmma::matrix_b, 16, 16, 16, __half, wmma::row_major> bfr;
                    wmma::load_matrix_sync(bfr, &sW[cur][(g * 32 + ks) * 72 + wn * 32 + p * 16], 72);
                    wmma::mma_sync(acc[g][p], af, bfr, acc[g][p]);
                }
        }
        if (it + 1 < NIT) {
            const int nxt = cur ^ 1;
            *(uint4*)&sH[nxt][hrow * 40 + hch] = hR;
            #pragma unroll
            for (int g = 0; g < 3; g++) *(uint4*)&sW[nxt][(g * 32 + wkr) * 72 + wch] = wR[g];
            __syncthreads();
        }
    }
    __syncthreads();   // repurpose smem as sC

    // epilogue: GRU nonlinearity; dual fp32 + fp16 h writes
    float* cw = &sCall[warp * 3 * 256];
    #pragma unroll
    for (int p = 0; p < 2; p++) {
        #pragma unroll
        for (int g = 0; g < 3; g++)
            wmma::store_matrix_sync(cw + g * 256, acc[g][p], 16, wmma::mem_row_major);
        __syncwarp();
        {
            int row = lane >> 1, c0 = (lane & 1) * 8;
            int b = b0 + wm * 16 + row;
            const __half* xr = xgt + (size_t)b * G3P;
            const float* hpr = hprev + (size_t)b * HP;
            float* hor = hout + (size_t)b * HP;
            __half* horh = houth + (size_t)b * HPH;
            #pragma unroll
            for (int q = 0; q < 8; q++) {
                int e = row * 16 + c0 + q;
                int j = j0 + wn * 32 + p * 16 + c0 + q;
                if (j < HH) {
                    float cr = cw[0 * 256 + e], cz = cw[1 * 256 + e], cn = cw[2 * 256 + e];
                    float r = 1.f / (1.f + __expf(-(__half2float(xr[j]) + cr + bhh[j])));
                    float z = 1.f / (1.f + __expf(-(__half2float(xr[HH + j]) + cz + bhh[HH + j])));
                    float nn = tanhf(__half2float(xr[2 * HH + j]) + r * (cn + bhh[2 * HH + j]));
                    float val = (1.f - z) * nn + z * hpr[j];
                    hor[j] = val;
                    horh[j] = H16(val);
                }
            }
        }
        __syncwarp();
    }
}

// =================== 3. word attention scores (fp16, double-buffered) ===================
// per block: fixed t, 64 b rows; 4 n-chunks of 128; K = 512 (16 slabs of 32). 8 warps 2x4.
__global__ __launch_bounds__(256, 2) void word_score3(
    const float* __restrict__ bw, const float* __restrict__ pw)
{
    __shared__ __half sA[2][64 * 40];
    __shared__ __half sB[2][32 * 136];
    __shared__ float  sC[8 * 256];
    __shared__ float  srow[64];

    const int t = blockIdx.x;
    const int b0 = blockIdx.y * 64;
    const int tid = threadIdx.x;
    const int warp = tid >> 5, lane = tid & 31;
    const int wm = warp >> 2, wn = warp & 3;

    const __half* hfh = g_hfh + (size_t)(t + 1) * BDIM * HPH;
    const __half* hrh = g_hrh + (size_t)t * BDIM * HPH;

    if (tid < 64) srow[tid] = 0.f;

    const int arow = tid >> 2, ach = (tid & 3) * 8;
    const __half* af_p = hfh + (size_t)(b0 + arow) * HPH + ach;
    const __half* ar_p = hrh + (size_t)(b0 + arow) * HPH + ach;
    const int bkr = tid >> 3, bch = (tid & 7) * 16;   // 2 uint4 per thread
    const int NIT = WKP / 32;  // 16

    for (int nc = 0; nc < 512; nc += 128) {
        wmma::fragment<wmma::accumulator, 16, 16, 16, float> acc[2][2];
        #pragma unroll
        for (int mi = 0; mi < 2; mi++)
            #pragma unroll
            for (int ni = 0; ni < 2; ni++) wmma::fill_fragment(acc[mi][ni], 0.f);

        uint4 aR = *(const uint4*)af_p;
        uint4 bR0 = *(const uint4*)&g_Ww[(size_t)bkr * WNP + nc + bch];
        uint4 bR1 = *(const uint4*)&g_Ww[(size_t)bkr * WNP + nc + bch + 8];

        __syncthreads();   // protect buf 0 from previous chunk's readers
        *(uint4*)&sA[0][arow * 40 + ach] = aR;
        *(uint4*)&sB[0][bkr * 136 + bch]     = bR0;
        *(uint4*)&sB[0][bkr * 136 + bch + 8] = bR1;
        __syncthreads();

        for (int it = 0; it < NIT; ++it) {
            const int cur = it & 1;
            if (it + 1 < NIT) {
                int k0 = (it + 1) * 32;
                aR = (k0 < HPH) ? *(const uint4*)(af_p + k0)
                                : *(const uint4*)(ar_p + (k0 - HPH));
                bR0 = *(const uint4*)&g_Ww[(size_t)(k0 + bkr) * WNP + nc + bch];
                bR1 = *(const uint4*)&g_Ww[(size_t)(k0 + bkr) * WNP + nc + bch + 8];
            }
            #pragma unroll
            for (int ks = 0; ks < 32; ks += 16) {
                wmma::fragment<wmma::matrix_a, 16, 16, 16, __half, wmma::row_major> af[2];
                #pragma unroll
                for (int mi = 0; mi < 2; mi++)
                    wmma::load_matrix_sync(af[mi], &sA[cur][(wm * 32 + mi * 16) * 40 + ks], 40);
                #pragma unroll
                for (int ni = 0; ni < 2; ni++) {
                    wmma::fragment<wmma::matrix_b, 16, 16, 16, __half, wmma::row_major> bfr;
                    wmma::load_matrix_sync(bfr, &sB[cur][ks * 136 + wn * 32 + ni * 16], 136);
                    #pragma unroll
                    for (int mi = 0; mi < 2; mi++)
                        wmma::mma_sync(acc[mi][ni], af[mi], bfr, acc[mi][ni]);
                }
            }
            if (it + 1 < NIT) {
                const int nxt = cur ^ 1;
                *(uint4*)&sA[nxt][arow * 40 + ach] = aR;
                *(uint4*)&sB[nxt][bkr * 136 + bch]     = bR0;
                *(uint4*)&sB[nxt][bkr * 136 + bch + 8] = bR1;
                __syncthreads();
            }
        }
        // fused epilogue: tanh(c + b) * proj, row-sum
        float* cw = &sC[warp * 256];
        #pragma unroll
        for (int mi = 0; mi < 2; mi++)
            #pragma unroll
            for (int ni = 0; ni < 2; ni++) {
                wmma::store_matrix_sync(cw, acc[mi][ni], 16, wmma::mem_row_major);
                __syncwarp();
                float part = 0.f;
                #pragma unroll
                for (int q = 0; q < 8; q++) {
                    int e = lane * 8 + q;
                    int col = e & 15;
                    int j = nc + wn * 32 + ni * 16 + col;
                    if (j < H2) part += tanhf(cw[e] + bw[j]) * pw[j];
                }
                atomicAdd(&srow[wm * 32 + mi * 16 + (lane >> 1)], part);
                __syncwarp();
            }
    }
    __syncthreads();
    if (tid < 64) g_scores[(size_t)(b0 + tid) * TT + t] = srow[tid];
}

// =================== 4. softmax over t + weighted sum (fp16 h reads) ===================
__global__ void word_attn()
{
    __shared__ float alpha[TT];
    __shared__ float red[2];
    const int b = blockIdx.x;
    const int tid = threadIdx.x;
    if (tid < TT) alpha[tid] = g_scores[(size_t)b * TT + tid];
    __syncthreads();
    if (tid == 0) {
        float m = -1e30f;
        for (int t2 = 0; t2 < TT; t2++) m = fmaxf(m, alpha[t2]);
        red[0] = m;
    }
    __syncthreads();
    if (tid < TT) alpha[tid] = __expf(alpha[tid] - red[0]);
    __syncthreads();
    if (tid == 0) {
        float ssum = 0.f;
        for (int t2 = 0; t2 < TT; t2++) ssum += alpha[t2];
        red[1] = 1.f / ssum;
    }
    __syncthreads();
    if (tid < TT) alpha[tid] *= red[1];
    __syncthreads();
    const size_t stride = (size_t)BDIM * HPH;
    for (int hcol = tid; hcol < H2; hcol += 256) {
        const __half* base = (hcol < HH)
            ? (g_hfh + stride + (size_t)b * HPH + hcol)          // slab t+1
            : (g_hrh + (size_t)b * HPH + (hcol - HH));           // slab t
        float acc = 0.f;
        #pragma unroll 4
        for (int t2 = 0; t2 < TT; t2++) acc += alpha[t2] * __half2float(base[(size_t)t2 * stride]);
        g_wordvec[(size_t)b * H2 + hcol] = acc;
    }
}

// =================== 5. zero output ===================
__global__ void zero_out(float* __restrict__ out, int n)
{
    int i = blockIdx.x * 256 + threadIdx.x;
    if (i < n) out[i] = 0.f;
}

// =================== 6. sentence attention + FC + scatter ===================
__global__ void sent_kernel(const float* __restrict__ Wsent, const float* __restrict__ bsent,
                            const float* __restrict__ psent, const float* __restrict__ fcW,
                            const float* __restrict__ fcb, const int* __restrict__ pairs,
                            float* __restrict__ out)
{
    __shared__ float wvs[MS][H2];
    __shared__ float score[MS];
    __shared__ float beta[MS];
    __shared__ float sv[H2];
    const int nb = blockIdx.x;
    const int tid = threadIdx.x;

    for (int i = tid; i < MS * H2; i += 256)
        wvs[i / H2][i % H2] = g_wordvec[(size_t)nb * MS * H2 + i];
    if (tid < MS) score[tid] = 0.f;
    __syncthreads();

    for (int j = tid; j < H2; j += 256) {
        float acc[MS];
        #pragma unroll
        for (int s = 0; s < MS; s++) acc[s] = 0.f;
        for (int k = 0; k < H2; k++) {
            float w = Wsent[(size_t)k * H2 + j];
            #pragma unroll
            for (int s = 0; s < MS; s++) acc[s] += wvs[s][k] * w;
        }
        float bb = bsent[j], pp = psent[j];
        #pragma unroll
        for (int s = 0; s < MS; s++) atomicAdd(&score[s], tanhf(acc[s] + bb) * pp);
    }
    __syncthreads();
    if (tid == 0) {
        float m = -1e30f;
        for (int s = 0; s < MS; s++) m = fmaxf(m, score[s]);
        float sum = 0.f;
        for (int s = 0; s < MS; s++) { beta[s] = __expf(score[s] - m); sum += beta[s]; }
        float inv = 1.f / sum;
        for (int s = 0; s < MS; s++) beta[s] *= inv;
    }
    __syncthreads();
    for (int hcol = tid; hcol < H2; hcol += 256) {
        float acc = 0.f;
        #pragma unroll
        for (int s = 0; s < MS; s++) acc += beta[s] * wvs[s][hcol];
        sv[hcol] = acc;
    }
    __syncthreads();
    if (tid < NOUT) {
        int o = tid;
        float acc = fcb[o];
        for (int k = 0; k < H2; k++) acc += sv[k] * fcW[(size_t)o * H2 + k];
        int p0 = pairs[nb * 3 + 0];
        int p1 = pairs[nb * 3 + 1];
        int p2 = pairs[nb * 3 + 2];
        out[(((size_t)p0 * NENT + p1) * NENT + p2) * NOUT + o] = acc;
    }
}

// =================== launcher ===================
extern "C" void kernel_launch(void* const* d_in, const int* in_sizes, int n_in,
                              void* d_out, int out_size)
{
    const float* bag       = (const float*)d_in[0];
    const float* W_ih_f    = (const float*)d_in[1];
    const float* W_hh_f    = (const float*)d_in[2];
    const float* b_ih_f    = (const float*)d_in[3];
    const float* b_hh_f    = (const float*)d_in[4];
    const float* W_ih_r    = (const float*)d_in[5];
    const float* W_hh_r    = (const float*)d_in[6];
    const float* b_ih_r    = (const float*)d_in[7];
    const float* b_hh_r    = (const float*)d_in[8];
    const float* W_word    = (const float*)d_in[9];
    const float* b_word    = (const float*)d_in[10];
    const float* proj_word = (const float*)d_in[11];
    const float* W_sent    = (const float*)d_in[12];
    const float* b_sent    = (const float*)d_in[13];
    const float* proj_sent = (const float*)d_in[14];
    const float* fc_W      = (const float*)d_in[15];
    const float* fc_b      = (const float*)d_in[16];
    const int*   pairs     = (const int*)d_in[17];
    float* out = (float*)d_out;

    // 0. pre-convert operands to fp16 MMA-ready layouts
    {
        size_t nx = (size_t)M_TOT * 46;
        conv_x<<<(unsigned)((nx + 255) / 256), 256>>>(bag);
        int nwih = 2 * 361 * G3;
        conv_wih<<<(nwih + 255) / 256, 256>>>(W_ih_f, b_ih_f, W_ih_r, b_ih_r);
        int nwhh = 2 * 3 * HH * HH;
        conv_whh<<<(nwhh + 255) / 256, 256>>>(W_hh_f, W_hh_r);
        int nww = WKP * H2;
        conv_ww<<<(nww + 255) / 256, 256>>>(W_word);
    }

    // 1. input GEMMs (bias folded via ones-column), BN=128, double-buffered
    dim3 gI(NXP / 128, M_TOT / 128, 2);
    input_gemm3<<<gI, 256>>>();

    // 2. 64 sequential GRU steps (fwd + rev concurrent per launch), double-buffered
    dim3 gS(4, BDIM / 64, 2);
    for (int s = 0; s < TT; s++)
        gru_step3<<<gS, 256>>>(b_hh_f, b_hh_r, s);

    // 3. word attention scores, double-buffered
    dim3 gW(TT, BDIM / 64);
    word_score3<<<gW, 256>>>(b_word, proj_word);

    // 4. softmax over t + word_vec
    word_attn<<<BDIM, 256>>>();

    // 5. zero output buffer
    int n_out = NDOCS * NENT * NENT * NOUT;
    zero_out<<<(n_out + 255) / 256, 256>>>(out, n_out);

    // 6. sentence attention + FC + scatter
    sent_kernel<<<NBAG, 256>>>(W_sent, b_sent, proj_sent, fc_W, fc_b, pairs, out);
}